// round 1
// baseline (speedup 1.0000x reference)
#include <cuda_runtime.h>
#include <math.h>

#define TOKENS 8192      // B*S
#define EMB    1024      // E
#define HD     1024      // H*D
#define HEADS  8
#define DIM    128
#define SEQ    2048
#define BATCH  4

// ---------------- scratch (static device globals: allocation-free) ----------
__device__ float g_z[TOKENS*HD];
__device__ float g_states[TOKENS*HD];
__device__ float g_hln[TOKENS*HD];
__device__ float g_h1[TOKENS*HD];
__device__ float g_wpre[TOKENS*EMB];
__device__ float g_logits[TOKENS*HEADS];
__device__ float g_scores[TOKENS*HEADS];
__device__ float g_v[HD];        // v_h[d] = sum_e W2[h,d,e]*w_att[e]
__device__ float g_c[HEADS];     // c_h    = sum_e b2[h,e]*w_att[e]
__device__ float g_osd[HD];      // diag of out_shaper

// ---------------- K0: precompute v, c, out_shaper diag ----------------------
__global__ void prep_kernel(const float* __restrict__ W2, const float* __restrict__ b2,
                            const float* __restrict__ watt, const float* __restrict__ osh)
{
    const int wid  = blockIdx.x * 8 + (threadIdx.x >> 5);
    const int lane = threadIdx.x & 31;
    if (wid < 1024) {
        const float* p = W2 + (size_t)wid * 1024;
        float s = 0.f;
        for (int e = lane; e < 1024; e += 32) s += p[e] * watt[e];
        #pragma unroll
        for (int o = 16; o; o >>= 1) s += __shfl_xor_sync(0xffffffffu, s, o);
        if (lane == 0) g_v[wid] = s;
    } else if (wid < 1032) {
        const int h = wid - 1024;
        const float* p = b2 + (size_t)h * 1024;
        float s = 0.f;
        for (int e = lane; e < 1024; e += 32) s += p[e] * watt[e];
        #pragma unroll
        for (int o = 16; o; o >>= 1) s += __shfl_xor_sync(0xffffffffu, s, o);
        if (lane == 0) g_c[h] = s;
    } else if (wid < 1040) {
        const int i0 = (wid - 1032) * 32 + lane;   // 0..255
        #pragma unroll
        for (int r = 0; r < 4; r++) {
            int j = i0 + r * 256;                  // 0..1023
            g_osd[j] = osh[(j >> 7) * 16384 + (j & 127) * 129];
        }
    }
}

// ---------------- big fp32 GEMM: 8192 x 1024 x 1024 -------------------------
// ACT==1: C = tanh(A@B + bias)   ACT==0: C = A@B
template<int ACT>
__global__ __launch_bounds__(256)
void gemm_big(const float* __restrict__ A, const float* __restrict__ Bm,
              const float* __restrict__ bias, float* __restrict__ C)
{
    const int K = 1024, N = 1024;
    __shared__ float As[2][1024];
    __shared__ float Bs[2][1024];
    const int t = threadIdx.x;
    const int m0 = blockIdx.y * 128, n0 = blockIdx.x * 128;
    const int arow = t >> 1, ak = (t & 1) * 4;
    const int brow = t >> 5, bn = (t & 31) * 4;
    const float* Ap = A + (size_t)(m0 + arow) * K + ak;
    const float* Bp = Bm + (size_t)brow * N + n0 + bn;
    float4 af = *(const float4*)Ap;
    float4 bf = *(const float4*)Bp;
    const int tx = t & 15, ty = t >> 4;
    float acc[8][8];
    #pragma unroll
    for (int i = 0; i < 8; i++)
        #pragma unroll
        for (int j = 0; j < 8; j++) acc[i][j] = 0.f;

    As[0][(ak+0)*128+arow] = af.x; As[0][(ak+1)*128+arow] = af.y;
    As[0][(ak+2)*128+arow] = af.z; As[0][(ak+3)*128+arow] = af.w;
    *(float4*)&Bs[0][brow*128+bn] = bf;
    __syncthreads();
    int buf = 0;
    for (int kt = 8; kt <= K; kt += 8) {
        const bool more = kt < K;
        if (more) {
            af = *(const float4*)(Ap + kt);
            bf = *(const float4*)(Bp + (size_t)kt * N);
        }
        #pragma unroll
        for (int kk = 0; kk < 8; kk++) {
            float4 a0 = *(const float4*)&As[buf][kk*128 + ty*8];
            float4 a1 = *(const float4*)&As[buf][kk*128 + ty*8 + 4];
            float4 b0 = *(const float4*)&Bs[buf][kk*128 + tx*8];
            float4 b1 = *(const float4*)&Bs[buf][kk*128 + tx*8 + 4];
            float aa[8] = {a0.x,a0.y,a0.z,a0.w,a1.x,a1.y,a1.z,a1.w};
            float bb[8] = {b0.x,b0.y,b0.z,b0.w,b1.x,b1.y,b1.z,b1.w};
            #pragma unroll
            for (int i = 0; i < 8; i++)
                #pragma unroll
                for (int j = 0; j < 8; j++)
                    acc[i][j] += aa[i] * bb[j];
        }
        if (more) {
            buf ^= 1;
            As[buf][(ak+0)*128+arow] = af.x; As[buf][(ak+1)*128+arow] = af.y;
            As[buf][(ak+2)*128+arow] = af.z; As[buf][(ak+3)*128+arow] = af.w;
            *(float4*)&Bs[buf][brow*128+bn] = bf;
            __syncthreads();
        }
    }
    float bv[8];
    if (ACT == 1) {
        float4 x0 = *(const float4*)&bias[n0 + tx*8];
        float4 x1 = *(const float4*)&bias[n0 + tx*8 + 4];
        bv[0]=x0.x; bv[1]=x0.y; bv[2]=x0.z; bv[3]=x0.w;
        bv[4]=x1.x; bv[5]=x1.y; bv[6]=x1.z; bv[7]=x1.w;
    }
    #pragma unroll
    for (int i = 0; i < 8; i++) {
        float o[8];
        #pragma unroll
        for (int j = 0; j < 8; j++) {
            float v = acc[i][j];
            if (ACT == 1) v = tanhf(v + bv[j]);
            o[j] = v;
        }
        float* cp = C + (size_t)(m0 + ty*8 + i) * N + n0 + tx*8;
        *(float4*)cp     = make_float4(o[0],o[1],o[2],o[3]);
        *(float4*)(cp+4) = make_float4(o[4],o[5],o[6],o[7]);
    }
}

// ---------------- sequential scan: one warp per (b,h) -----------------------
__global__ void scan_kernel(const float* __restrict__ Uh, const float* __restrict__ Uz,
                            const float* __restrict__ bu, const float* __restrict__ lg,
                            const float* __restrict__ lb)
{
    const int seq  = blockIdx.x;         // 0..31
    const int lane = threadIdx.x;        // 0..31
    const int b = seq >> 3, h = seq & 7;
    const int d0 = lane * 4;
    float uh[4], uz[4], bb[4], gg[4], be[4];
    #pragma unroll
    for (int i = 0; i < 4; i++) {
        int d = d0 + i;
        uh[i] = Uh[h*16384 + d*129];     // diagonal element
        uz[i] = Uz[h*16384 + d*129];
        bb[i] = bu[h*128 + d];
        gg[i] = lg[d];
        be[i] = lb[d];
    }
    const size_t base = (size_t)b * SEQ * HD + h * 128 + d0;
    const float4* zp = (const float4*)(g_z + base);
    float4* sp = (float4*)(g_states + base);
    float hp[4] = {0.f, 0.f, 0.f, 0.f};
    float4 zc = zp[0];
    for (int s = 0; s < SEQ; s++) {
        float4 zn = make_float4(0.f, 0.f, 0.f, 0.f);
        if (s + 1 < SEQ) zn = zp[(size_t)(s + 1) * 256];
        float zt[4] = {zc.x, zc.y, zc.z, zc.w};
        float hn[4]; float sum = 0.f, sq = 0.f;
        #pragma unroll
        for (int i = 0; i < 4; i++) {
            float a = hp[i]*uh[i] + zt[i]*uz[i] + bb[i];
            float u = __fdividef(1.f, 1.f + __expf(-a));
            float v = u*hp[i] + (1.f - u)*zt[i];
            hn[i] = v; sum += v; sq += v*v;
        }
        #pragma unroll
        for (int o = 16; o; o >>= 1) {
            sum += __shfl_xor_sync(0xffffffffu, sum, o);
            sq  += __shfl_xor_sync(0xffffffffu, sq, o);
        }
        float m = sum * (1.f/128.f);
        float inv = rsqrtf(sq * (1.f/128.f) - m*m + 1e-5f);
        #pragma unroll
        for (int i = 0; i < 4; i++) hp[i] = (hn[i]-m)*inv*gg[i] + be[i];
        sp[(size_t)s * 256] = make_float4(hp[0], hp[1], hp[2], hp[3]);
        zc = zn;
    }
}

// ---------------- K3a: shaped = state * os_diag, per-head LN ----------------
__global__ __launch_bounds__(256)
void hln_kernel(const float* __restrict__ fg, const float* __restrict__ fb)
{
    const int w    = (blockIdx.x << 3) + (threadIdx.x >> 5);  // row over B*S*H
    const int lane = threadIdx.x & 31;
    const int h = w & 7;
    float4 x  = ((const float4*)(g_states + (size_t)w * 128))[lane];
    float4 od = ((const float4*)g_osd)[h*32 + lane];
    x.x *= od.x; x.y *= od.y; x.z *= od.z; x.w *= od.w;
    float sum = x.x + x.y + x.z + x.w;
    float sq  = x.x*x.x + x.y*x.y + x.z*x.z + x.w*x.w;
    #pragma unroll
    for (int o = 16; o; o >>= 1) {
        sum += __shfl_xor_sync(0xffffffffu, sum, o);
        sq  += __shfl_xor_sync(0xffffffffu, sq, o);
    }
    float m = sum * (1.f/128.f);
    float inv = rsqrtf(sq * (1.f/128.f) - m*m + 1e-5f);
    float4 gg = ((const float4*)fg)[h*32 + lane];
    float4 bb = ((const float4*)fb)[h*32 + lane];
    float4 y;
    y.x = (x.x-m)*inv*gg.x + bb.x;
    y.y = (x.y-m)*inv*gg.y + bb.y;
    y.z = (x.z-m)*inv*gg.z + bb.z;
    y.w = (x.w-m)*inv*gg.w + bb.w;
    ((float4*)(g_hln + (size_t)w * 128))[lane] = y;
}

// ---------------- K3b: per-head GEMM + GELU + logits ------------------------
// h1[t,h,:] = gelu(hln[t,h,:] @ W1[h] + b1[h]); logit[t,h] = h1·v_h + c_h + b_att
__global__ __launch_bounds__(256)
void ffn1_kernel(const float* __restrict__ W1, const float* __restrict__ b1,
                 const float* __restrict__ batt)
{
    __shared__ float As[2][1024];
    __shared__ float Bs[2][1024];
    __shared__ float red[128*17];
    const int t = threadIdx.x;
    const int m0 = blockIdx.x * 128;
    const int h  = blockIdx.y;
    const int arow = t >> 1, ak = (t & 1) * 4;
    const int brow = t >> 5, bn = (t & 31) * 4;
    const float* Ap = g_hln + (size_t)(m0 + arow) * HD + h * 128 + ak;
    const float* Bp = W1 + h * 16384 + brow * 128 + bn;
    float4 af = *(const float4*)Ap;
    float4 bf = *(const float4*)Bp;
    const int tx = t & 15, ty = t >> 4;
    float acc[8][8];
    #pragma unroll
    for (int i = 0; i < 8; i++)
        #pragma unroll
        for (int j = 0; j < 8; j++) acc[i][j] = 0.f;

    As[0][(ak+0)*128+arow] = af.x; As[0][(ak+1)*128+arow] = af.y;
    As[0][(ak+2)*128+arow] = af.z; As[0][(ak+3)*128+arow] = af.w;
    *(float4*)&Bs[0][brow*128+bn] = bf;
    __syncthreads();
    int buf = 0;
    for (int kt = 8; kt <= 128; kt += 8) {
        const bool more = kt < 128;
        if (more) {
            af = *(const float4*)(Ap + kt);
            bf = *(const float4*)(Bp + kt * 128);
        }
        #pragma unroll
        for (int kk = 0; kk < 8; kk++) {
            float4 a0 = *(const float4*)&As[buf][kk*128 + ty*8];
            float4 a1 = *(const float4*)&As[buf][kk*128 + ty*8 + 4];
            float4 b0 = *(const float4*)&Bs[buf][kk*128 + tx*8];
            float4 b1 = *(const float4*)&Bs[buf][kk*128 + tx*8 + 4];
            float aa[8] = {a0.x,a0.y,a0.z,a0.w,a1.x,a1.y,a1.z,a1.w};
            float bb[8] = {b0.x,b0.y,b0.z,b0.w,b1.x,b1.y,b1.z,b1.w};
            #pragma unroll
            for (int i = 0; i < 8; i++)
                #pragma unroll
                for (int j = 0; j < 8; j++)
                    acc[i][j] += aa[i] * bb[j];
        }
        if (more) {
            buf ^= 1;
            As[buf][(ak+0)*128+arow] = af.x; As[buf][(ak+1)*128+arow] = af.y;
            As[buf][(ak+2)*128+arow] = af.z; As[buf][(ak+3)*128+arow] = af.w;
            *(float4*)&Bs[buf][brow*128+bn] = bf;
            __syncthreads();
        }
    }
    float bvals[8], vv[8];
    {
        float4 x0 = *(const float4*)&b1[h*128 + tx*8];
        float4 x1 = *(const float4*)&b1[h*128 + tx*8 + 4];
        bvals[0]=x0.x; bvals[1]=x0.y; bvals[2]=x0.z; bvals[3]=x0.w;
        bvals[4]=x1.x; bvals[5]=x1.y; bvals[6]=x1.z; bvals[7]=x1.w;
        float4 v0 = *(const float4*)&g_v[h*128 + tx*8];
        float4 v1 = *(const float4*)&g_v[h*128 + tx*8 + 4];
        vv[0]=v0.x; vv[1]=v0.y; vv[2]=v0.z; vv[3]=v0.w;
        vv[4]=v1.x; vv[5]=v1.y; vv[6]=v1.z; vv[7]=v1.w;
    }
    const float cadd = g_c[h] + batt[0];
    #pragma unroll
    for (int i = 0; i < 8; i++) {
        float o[8]; float lp = 0.f;
        #pragma unroll
        for (int j = 0; j < 8; j++) {
            float xv = acc[i][j] + bvals[j];
            float gel = 0.5f * xv * (1.f + erff(xv * 0.70710678118654752f));
            o[j] = gel; lp += gel * vv[j];
        }
        float* cp = g_h1 + (size_t)(m0 + ty*8 + i) * HD + h * 128 + tx*8;
        *(float4*)cp     = make_float4(o[0],o[1],o[2],o[3]);
        *(float4*)(cp+4) = make_float4(o[4],o[5],o[6],o[7]);
        red[(ty*8 + i)*17 + tx] = lp;
    }
    __syncthreads();
    if (t < 128) {
        float s = 0.f;
        #pragma unroll
        for (int x = 0; x < 16; x++) s += red[t*17 + x];
        g_logits[(size_t)(m0 + t) * 8 + h] = s + cadd;
    }
}

// ---------------- K3c: softmax over heads, scale h1 in place ----------------
__global__ void softscale_kernel()
{
    const int tok = blockIdx.x;
    const int t = threadIdx.x;   // 128
    float l[8];
    #pragma unroll
    for (int h = 0; h < 8; h++) l[h] = g_logits[tok*8 + h];
    float mx = l[0];
    #pragma unroll
    for (int h = 1; h < 8; h++) mx = fmaxf(mx, l[h]);
    float e[8]; float s = 0.f;
    #pragma unroll
    for (int h = 0; h < 8; h++) { e[h] = __expf(l[h] - mx); s += e[h]; }
    const float inv = __fdividef(1.f, s);
    float p[8];
    #pragma unroll
    for (int h = 0; h < 8; h++) p[h] = e[h] * inv;
    const size_t base = (size_t)tok * HD;
    #pragma unroll
    for (int r = 0; r < 8; r++) g_h1[base + r*128 + t] *= p[r];
    if (t < 8) g_scores[tok*8 + t] = p[t];
}

// ---------------- K5: weighted = wpre + scores@b2, output LN ----------------
__global__ __launch_bounds__(256)
void final_kernel(const float* __restrict__ b2, const float* __restrict__ lno_g,
                  const float* __restrict__ lno_b, float* __restrict__ out)
{
    __shared__ float b2s[8192];
    __shared__ float sc[8];
    __shared__ float rs[8], rq[8];
    const int t = threadIdx.x;
    for (int i = t; i < 2048; i += 256)
        ((float4*)b2s)[i] = ((const float4*)b2)[i];
    float4 lg = ((const float4*)lno_g)[t];
    float4 lb = ((const float4*)lno_b)[t];
    for (int tk = 0; tk < 16; tk++) {
        const int token = blockIdx.x * 16 + tk;
        __syncthreads();
        if (t < 8) sc[t] = g_scores[token*8 + t];
        __syncthreads();
        float4 w = ((const float4*)(g_wpre + (size_t)token * 1024))[t];
        float y0 = w.x, y1 = w.y, y2 = w.z, y3 = w.w;
        #pragma unroll
        for (int h = 0; h < 8; h++) {
            float s = sc[h];
            float4 bv = ((float4*)b2s)[h*256 + t];
            y0 += s*bv.x; y1 += s*bv.y; y2 += s*bv.z; y3 += s*bv.w;
        }
        float sum = y0 + y1 + y2 + y3;
        float sq  = y0*y0 + y1*y1 + y2*y2 + y3*y3;
        #pragma unroll
        for (int o = 16; o; o >>= 1) {
            sum += __shfl_xor_sync(0xffffffffu, sum, o);
            sq  += __shfl_xor_sync(0xffffffffu, sq, o);
        }
        const int wid = t >> 5;
        if ((t & 31) == 0) { rs[wid] = sum; rq[wid] = sq; }
        __syncthreads();
        float ts = 0.f, tq = 0.f;
        #pragma unroll
        for (int i = 0; i < 8; i++) { ts += rs[i]; tq += rq[i]; }
        const float m = ts * (1.f/1024.f);
        const float inv = rsqrtf(tq * (1.f/1024.f) - m*m + 1e-5f);
        float4 o;
        o.x = (y0-m)*inv*lg.x + lb.x;
        o.y = (y1-m)*inv*lg.y + lb.y;
        o.z = (y2-m)*inv*lg.z + lb.z;
        o.w = (y3-m)*inv*lg.w + lb.w;
        ((float4*)(out + (size_t)token * 1024))[t] = o;
    }
}

// ---------------- launch --------------------------------------------------
extern "C" void kernel_launch(void* const* d_in, const int* in_sizes, int n_in,
                              void* d_out, int out_size)
{
    const float* x     = (const float*)d_in[0];
    const float* W_ez  = (const float*)d_in[1];
    const float* b_ez  = (const float*)d_in[2];
    const float* U_h   = (const float*)d_in[3];
    const float* U_z   = (const float*)d_in[4];
    const float* b_u   = (const float*)d_in[5];
    const float* osh   = (const float*)d_in[6];
    const float* lns_g = (const float*)d_in[7];
    const float* lns_b = (const float*)d_in[8];
    const float* ffg   = (const float*)d_in[9];
    const float* ffb   = (const float*)d_in[10];
    const float* W1    = (const float*)d_in[11];
    const float* b1    = (const float*)d_in[12];
    const float* W2    = (const float*)d_in[13];
    const float* b2    = (const float*)d_in[14];
    const float* watt  = (const float*)d_in[15];
    const float* batt  = (const float*)d_in[16];
    const float* lno_g = (const float*)d_in[17];
    const float* lno_b = (const float*)d_in[18];
    float* out = (float*)d_out;

    float *gz, *gh1, *gwpre;
    cudaGetSymbolAddress((void**)&gz,    g_z);
    cudaGetSymbolAddress((void**)&gh1,   g_h1);
    cudaGetSymbolAddress((void**)&gwpre, g_wpre);

    prep_kernel<<<130, 256>>>(W2, b2, watt, osh);

    dim3 gg(8, 64);  // (N/128, M/128)
    gemm_big<1><<<gg, 256>>>(x, W_ez, b_ez, gz);

    scan_kernel<<<32, 32>>>(U_h, U_z, b_u, lns_g, lns_b);

    hln_kernel<<<8192, 256>>>(ffg, ffb);

    dim3 gf(64, 8);  // (M/128, heads)
    ffn1_kernel<<<gf, 256>>>(W1, b1, batt);

    softscale_kernel<<<8192, 128>>>();

    gemm_big<0><<<gg, 256>>>(gh1, W2, nullptr, gwpre);

    final_kernel<<<512, 256>>>(b2, lno_g, lno_b, out);
}

// round 3
// speedup vs baseline: 1.4323x; 1.4323x over previous
#include <cuda_runtime.h>
#include <math.h>
#include <stdint.h>

#define TOKENS 8192      // B*S
#define EMB    1024      // E
#define HD     1024      // H*D
#define HEADS  8
#define DIM    128
#define SEQ    2048
#define BATCH  4

// ---------------- scratch (static device globals: allocation-free) ----------
__device__ float g_z[TOKENS*HD];
__device__ float g_states[TOKENS*HD];
__device__ float g_hln[TOKENS*HD];
__device__ float g_h1[TOKENS*HD];
__device__ float g_wpre[TOKENS*EMB];
__device__ float g_xr[TOKENS*EMB];     // tf32-rounded x
__device__ float g_wezr[EMB*HD];       // tf32-rounded W_ez
__device__ float g_w2r[HD*EMB];        // tf32-rounded W2
__device__ float g_logits[TOKENS*HEADS];
__device__ float g_scores[TOKENS*HEADS];
__device__ float g_v[HD];        // v_h[d] = sum_e W2[h,d,e]*w_att[e]
__device__ float g_c[HEADS];     // c_h    = sum_e b2[h,e]*w_att[e]
__device__ float g_osd[HD];      // diag of out_shaper

// ---------------- helpers ---------------------------------------------------
__device__ __forceinline__ float round_tf32f(float x) {
    uint32_t r;
    asm("cvt.rna.tf32.f32 %0, %1;" : "=r"(r) : "f"(x));
    return __uint_as_float(r);
}
__device__ __forceinline__ uint32_t smem_u32(const void* p) {
    return (uint32_t)__cvta_generic_to_shared(p);
}
__device__ __forceinline__ void cp16(uint32_t s, const void* g) {
    asm volatile("cp.async.ca.shared.global [%0], [%1], 16;\n" :: "r"(s), "l"(g));
}
__device__ __forceinline__ float warp_sum(float v) {
    #pragma unroll
    for (int o = 16; o; o >>= 1) v += __shfl_xor_sync(0xffffffffu, v, o);
    return v;
}
__device__ __forceinline__ void mma_tf32(float* c, const uint32_t* a, const uint32_t* b) {
    asm volatile(
        "mma.sync.aligned.m16n8k8.row.col.f32.tf32.tf32.f32 "
        "{%0,%1,%2,%3}, {%4,%5,%6,%7}, {%8,%9}, {%0,%1,%2,%3};\n"
        : "+f"(c[0]), "+f"(c[1]), "+f"(c[2]), "+f"(c[3])
        : "r"(a[0]), "r"(a[1]), "r"(a[2]), "r"(a[3]), "r"(b[0]), "r"(b[1]));
}

// ---------------- K-1: round fp32 -> tf32 (elementwise) ---------------------
__global__ void round_tf32_kernel(const float4* __restrict__ in, float4* __restrict__ out, int n4)
{
    int i = blockIdx.x * blockDim.x + threadIdx.x;
    if (i < n4) {
        float4 v = in[i];
        v.x = round_tf32f(v.x); v.y = round_tf32f(v.y);
        v.z = round_tf32f(v.z); v.w = round_tf32f(v.w);
        out[i] = v;
    }
}

// ---------------- K0: precompute v, c, out_shaper diag ----------------------
__global__ void prep_kernel(const float* __restrict__ W2, const float* __restrict__ b2,
                            const float* __restrict__ watt, const float* __restrict__ osh)
{
    const int wid  = blockIdx.x * 8 + (threadIdx.x >> 5);
    const int lane = threadIdx.x & 31;
    if (wid < 1024) {
        const float* p = W2 + (size_t)wid * 1024;
        float s = 0.f;
        for (int e = lane; e < 1024; e += 32) s += p[e] * watt[e];
        s = warp_sum(s);
        if (lane == 0) g_v[wid] = s;
    } else if (wid < 1032) {
        const int h = wid - 1024;
        const float* p = b2 + (size_t)h * 1024;
        float s = 0.f;
        for (int e = lane; e < 1024; e += 32) s += p[e] * watt[e];
        s = warp_sum(s);
        if (lane == 0) g_c[h] = s;
    } else if (wid < 1040) {
        const int i0 = (wid - 1032) * 32 + lane;   // 0..255
        #pragma unroll
        for (int r = 0; r < 4; r++) {
            int j = i0 + r * 256;                  // 0..1023
            g_osd[j] = osh[(j >> 7) * 16384 + (j & 127) * 129];
        }
    }
}

// ---------------- tf32 tensor-core GEMM: 8192 x 1024 x 1024 -----------------
// ACT==1: C = tanh(A@B + bias)   ACT==0: C = A@B
// A,B must be pre-rounded to tf32. Block tile 128x128, K-tile 32, cp.async
// double-buffered. 8 warps as 4(M)x2(N); warp tile 32x64 via m16n8k8.
#define AS_PITCH 36
#define BS_PITCH 132
#define AS_FLOATS (128*AS_PITCH)        // 4608
#define BS_FLOATS (32*BS_PITCH)         // 4224
#define GEMM_SMEM_BYTES ((2*AS_FLOATS + 2*BS_FLOATS) * 4)   // 70656

#define LOAD_TILE(buf, kb)                                                     \
    {                                                                          \
        float* Asb = dsm + (buf) * AS_FLOATS;                                  \
        float* Bsb = dsm + 2 * AS_FLOATS + (buf) * BS_FLOATS;                  \
        _Pragma("unroll")                                                      \
        for (int p = 0; p < 4; p++) {                                          \
            int idx = t + p * 256;                                             \
            int r  = idx >> 3, c  = (idx & 7) * 4;                             \
            cp16(smem_u32(Asb + r * AS_PITCH + c),                             \
                 A + (size_t)(m0 + r) * 1024 + (kb) + c);                      \
            int r2 = idx >> 5, c2 = (idx & 31) * 4;                            \
            cp16(smem_u32(Bsb + r2 * BS_PITCH + c2),                           \
                 Bm + (size_t)((kb) + r2) * 1024 + n0 + c2);                   \
        }                                                                      \
        asm volatile("cp.async.commit_group;\n");                              \
    }

template<int ACT>
__global__ __launch_bounds__(256)
void gemm_tf32(const float* __restrict__ A, const float* __restrict__ Bm,
               const float* __restrict__ bias, float* __restrict__ C)
{
    extern __shared__ float dsm[];
    const int t = threadIdx.x;
    const int m0 = blockIdx.y * 128, n0 = blockIdx.x * 128;
    const int lane = t & 31, wid = t >> 5;
    const int gid = lane >> 2, tig = lane & 3;
    const int mrow = (wid >> 1) * 32, ncol = (wid & 1) * 64;

    float acc[2][8][4];
    #pragma unroll
    for (int mi = 0; mi < 2; mi++)
        #pragma unroll
        for (int ni = 0; ni < 8; ni++)
            #pragma unroll
            for (int q = 0; q < 4; q++) acc[mi][ni][q] = 0.f;

    LOAD_TILE(0, 0);
    LOAD_TILE(1, 32);

    const int NT = 32;   // 1024/32 K-tiles
    for (int kt = 0; kt < NT; kt++) {
        const int buf = kt & 1;
        if (kt + 1 < NT) { asm volatile("cp.async.wait_group 1;\n"); }
        else             { asm volatile("cp.async.wait_group 0;\n"); }
        __syncthreads();

        const uint32_t* As32 = (const uint32_t*)(dsm + buf * AS_FLOATS);
        const uint32_t* Bs32 = (const uint32_t*)(dsm + 2 * AS_FLOATS + buf * BS_FLOATS);
        #pragma unroll
        for (int kf = 0; kf < 4; kf++) {
            const int k8 = kf * 8;
            uint32_t a[2][4], b[8][2];
            #pragma unroll
            for (int mi = 0; mi < 2; mi++) {
                const uint32_t* ap = As32 + (mrow + mi * 16 + gid) * AS_PITCH + k8 + tig;
                a[mi][0] = ap[0];
                a[mi][1] = ap[8 * AS_PITCH];
                a[mi][2] = ap[4];
                a[mi][3] = ap[8 * AS_PITCH + 4];
            }
            #pragma unroll
            for (int ni = 0; ni < 8; ni++) {
                const uint32_t* bp = Bs32 + (k8 + tig) * BS_PITCH + ncol + ni * 8 + gid;
                b[ni][0] = bp[0];
                b[ni][1] = bp[4 * BS_PITCH];
            }
            #pragma unroll
            for (int mi = 0; mi < 2; mi++)
                #pragma unroll
                for (int ni = 0; ni < 8; ni++)
                    mma_tf32(acc[mi][ni], a[mi], b[ni]);
        }
        __syncthreads();
        if (kt + 2 < NT) { LOAD_TILE(buf, (kt + 2) * 32); }
    }

    // epilogue
    #pragma unroll
    for (int mi = 0; mi < 2; mi++) {
        const int row = m0 + mrow + mi * 16 + gid;
        #pragma unroll
        for (int ni = 0; ni < 8; ni++) {
            const int col = n0 + ncol + ni * 8 + 2 * tig;
            float v0 = acc[mi][ni][0], v1 = acc[mi][ni][1];
            float v2 = acc[mi][ni][2], v3 = acc[mi][ni][3];
            if (ACT == 1) {
                const float b0 = bias[col], b1 = bias[col + 1];
                v0 = tanhf(v0 + b0); v1 = tanhf(v1 + b1);
                v2 = tanhf(v2 + b0); v3 = tanhf(v3 + b1);
            }
            *(float2*)(C + (size_t)row * 1024 + col)       = make_float2(v0, v1);
            *(float2*)(C + (size_t)(row + 8) * 1024 + col) = make_float2(v2, v3);
        }
    }
}

// ---------------- sequential scan: one warp per (b,h) -----------------------
__global__ void scan_kernel(const float* __restrict__ Uh, const float* __restrict__ Uz,
                            const float* __restrict__ bu, const float* __restrict__ lg,
                            const float* __restrict__ lb)
{
    const int seq  = blockIdx.x;         // 0..31
    const int lane = threadIdx.x;        // 0..31
    const int b = seq >> 3, h = seq & 7;
    const int d0 = lane * 4;
    float uh[4], uz[4], bb[4], gg[4], be[4];
    #pragma unroll
    for (int i = 0; i < 4; i++) {
        int d = d0 + i;
        uh[i] = Uh[h*16384 + d*129];     // diagonal element
        uz[i] = Uz[h*16384 + d*129];
        bb[i] = bu[h*128 + d];
        gg[i] = lg[d];
        be[i] = lb[d];
    }
    const size_t base = (size_t)b * SEQ * HD + h * 128 + d0;
    const float4* zp = (const float4*)(g_z + base);
    float4* sp = (float4*)(g_states + base);
    float hp[4] = {0.f, 0.f, 0.f, 0.f};
    float4 zc = zp[0];
    for (int s = 0; s < SEQ; s++) {
        float4 zn = make_float4(0.f, 0.f, 0.f, 0.f);
        if (s + 1 < SEQ) zn = zp[(size_t)(s + 1) * 256];
        float zt[4] = {zc.x, zc.y, zc.z, zc.w};
        float hn[4]; float sum = 0.f, sq = 0.f;
        #pragma unroll
        for (int i = 0; i < 4; i++) {
            float a = hp[i]*uh[i] + zt[i]*uz[i] + bb[i];
            float u = __fdividef(1.f, 1.f + __expf(-a));
            float v = u*hp[i] + (1.f - u)*zt[i];
            hn[i] = v; sum += v; sq += v*v;
        }
        #pragma unroll
        for (int o = 16; o; o >>= 1) {
            sum += __shfl_xor_sync(0xffffffffu, sum, o);
            sq  += __shfl_xor_sync(0xffffffffu, sq, o);
        }
        float m = sum * (1.f/128.f);
        float inv = rsqrtf(sq * (1.f/128.f) - m*m + 1e-5f);
        #pragma unroll
        for (int i = 0; i < 4; i++) hp[i] = (hn[i]-m)*inv*gg[i] + be[i];
        sp[(size_t)s * 256] = make_float4(hp[0], hp[1], hp[2], hp[3]);
        zc = zn;
    }
}

// ---------------- K3a: shaped = state * os_diag, per-head LN ----------------
__global__ __launch_bounds__(256)
void hln_kernel(const float* __restrict__ fg, const float* __restrict__ fb)
{
    const int w    = (blockIdx.x << 3) + (threadIdx.x >> 5);  // row over B*S*H
    const int lane = threadIdx.x & 31;
    const int h = w & 7;
    float4 x  = ((const float4*)(g_states + (size_t)w * 128))[lane];
    float4 od = ((const float4*)g_osd)[h*32 + lane];
    x.x *= od.x; x.y *= od.y; x.z *= od.z; x.w *= od.w;
    float sum = x.x + x.y + x.z + x.w;
    float sq  = x.x*x.x + x.y*x.y + x.z*x.z + x.w*x.w;
    #pragma unroll
    for (int o = 16; o; o >>= 1) {
        sum += __shfl_xor_sync(0xffffffffu, sum, o);
        sq  += __shfl_xor_sync(0xffffffffu, sq, o);
    }
    float m = sum * (1.f/128.f);
    float inv = rsqrtf(sq * (1.f/128.f) - m*m + 1e-5f);
    float4 gg = ((const float4*)fg)[h*32 + lane];
    float4 bb = ((const float4*)fb)[h*32 + lane];
    float4 y;
    y.x = (x.x-m)*inv*gg.x + bb.x;
    y.y = (x.y-m)*inv*gg.y + bb.y;
    y.z = (x.z-m)*inv*gg.z + bb.z;
    y.w = (x.w-m)*inv*gg.w + bb.w;
    ((float4*)(g_hln + (size_t)w * 128))[lane] = y;
}

// ---------------- K3b: per-head GEMM + GELU + logits ------------------------
__global__ __launch_bounds__(256)
void ffn1_kernel(const float* __restrict__ W1, const float* __restrict__ b1,
                 const float* __restrict__ batt)
{
    __shared__ float As[2][1024];
    __shared__ float Bs[2][1024];
    __shared__ float red[128*17];
    const int t = threadIdx.x;
    const int m0 = blockIdx.x * 128;
    const int h  = blockIdx.y;
    const int arow = t >> 1, ak = (t & 1) * 4;
    const int brow = t >> 5, bn = (t & 31) * 4;
    const float* Ap = g_hln + (size_t)(m0 + arow) * HD + h * 128 + ak;
    const float* Bp = W1 + h * 16384 + brow * 128 + bn;
    float4 af = *(const float4*)Ap;
    float4 bf = *(const float4*)Bp;
    const int tx = t & 15, ty = t >> 4;
    float acc[8][8];
    #pragma unroll
    for (int i = 0; i < 8; i++)
        #pragma unroll
        for (int j = 0; j < 8; j++) acc[i][j] = 0.f;

    As[0][(ak+0)*128+arow] = af.x; As[0][(ak+1)*128+arow] = af.y;
    As[0][(ak+2)*128+arow] = af.z; As[0][(ak+3)*128+arow] = af.w;
    *(float4*)&Bs[0][brow*128+bn] = bf;
    __syncthreads();
    int buf = 0;
    for (int kt = 8; kt <= 128; kt += 8) {
        const bool more = kt < 128;
        if (more) {
            af = *(const float4*)(Ap + kt);
            bf = *(const float4*)(Bp + kt * 128);
        }
        #pragma unroll
        for (int kk = 0; kk < 8; kk++) {
            float4 a0 = *(const float4*)&As[buf][kk*128 + ty*8];
            float4 a1 = *(const float4*)&As[buf][kk*128 + ty*8 + 4];
            float4 b0 = *(const float4*)&Bs[buf][kk*128 + tx*8];
            float4 b1 = *(const float4*)&Bs[buf][kk*128 + tx*8 + 4];
            float aa[8] = {a0.x,a0.y,a0.z,a0.w,a1.x,a1.y,a1.z,a1.w};
            float bb[8] = {b0.x,b0.y,b0.z,b0.w,b1.x,b1.y,b1.z,b1.w};
            #pragma unroll
            for (int i = 0; i < 8; i++)
                #pragma unroll
                for (int j = 0; j < 8; j++)
                    acc[i][j] += aa[i] * bb[j];
        }
        if (more) {
            buf ^= 1;
            As[buf][(ak+0)*128+arow] = af.x; As[buf][(ak+1)*128+arow] = af.y;
            As[buf][(ak+2)*128+arow] = af.z; As[buf][(ak+3)*128+arow] = af.w;
            *(float4*)&Bs[buf][brow*128+bn] = bf;
            __syncthreads();
        }
    }
    float bvals[8], vv[8];
    {
        float4 x0 = *(const float4*)&b1[h*128 + tx*8];
        float4 x1 = *(const float4*)&b1[h*128 + tx*8 + 4];
        bvals[0]=x0.x; bvals[1]=x0.y; bvals[2]=x0.z; bvals[3]=x0.w;
        bvals[4]=x1.x; bvals[5]=x1.y; bvals[6]=x1.z; bvals[7]=x1.w;
        float4 v0 = *(const float4*)&g_v[h*128 + tx*8];
        float4 v1 = *(const float4*)&g_v[h*128 + tx*8 + 4];
        vv[0]=v0.x; vv[1]=v0.y; vv[2]=v0.z; vv[3]=v0.w;
        vv[4]=v1.x; vv[5]=v1.y; vv[6]=v1.z; vv[7]=v1.w;
    }
    const float cadd = g_c[h] + batt[0];
    #pragma unroll
    for (int i = 0; i < 8; i++) {
        float o[8]; float lp = 0.f;
        #pragma unroll
        for (int j = 0; j < 8; j++) {
            float xv = acc[i][j] + bvals[j];
            float gel = 0.5f * xv * (1.f + erff(xv * 0.70710678118654752f));
            o[j] = gel; lp += gel * vv[j];
        }
        float* cp = g_h1 + (size_t)(m0 + ty*8 + i) * HD + h * 128 + tx*8;
        *(float4*)cp     = make_float4(o[0],o[1],o[2],o[3]);
        *(float4*)(cp+4) = make_float4(o[4],o[5],o[6],o[7]);
        red[(ty*8 + i)*17 + tx] = lp;
    }
    __syncthreads();
    if (t < 128) {
        float s = 0.f;
        #pragma unroll
        for (int x = 0; x < 16; x++) s += red[t*17 + x];
        g_logits[(size_t)(m0 + t) * 8 + h] = s + cadd;
    }
}

// ---------------- K3c: softmax over heads, scale h1 (tf32-rounded) ----------
__global__ void softscale_kernel()
{
    const int tok = blockIdx.x;
    const int t = threadIdx.x;   // 128
    float l[8];
    #pragma unroll
    for (int h = 0; h < 8; h++) l[h] = g_logits[tok*8 + h];
    float mx = l[0];
    #pragma unroll
    for (int h = 1; h < 8; h++) mx = fmaxf(mx, l[h]);
    float e[8]; float s = 0.f;
    #pragma unroll
    for (int h = 0; h < 8; h++) { e[h] = __expf(l[h] - mx); s += e[h]; }
    const float inv = __fdividef(1.f, s);
    float p[8];
    #pragma unroll
    for (int h = 0; h < 8; h++) p[h] = e[h] * inv;
    const size_t base = (size_t)tok * HD;
    #pragma unroll
    for (int r = 0; r < 8; r++)
        g_h1[base + r*128 + t] = round_tf32f(g_h1[base + r*128 + t] * p[r]);
    if (t < 8) g_scores[tok*8 + t] = p[t];
}

// ---------------- K5: weighted = wpre + scores@b2, output LN ----------------
__global__ __launch_bounds__(256)
void final_kernel(const float* __restrict__ b2, const float* __restrict__ lno_g,
                  const float* __restrict__ lno_b, float* __restrict__ out)
{
    __shared__ float b2s[8192];
    __shared__ float sc[8];
    __shared__ float rs[8], rq[8];
    const int t = threadIdx.x;
    for (int i = t; i < 2048; i += 256)
        ((float4*)b2s)[i] = ((const float4*)b2)[i];
    float4 lg = ((const float4*)lno_g)[t];
    float4 lb = ((const float4*)lno_b)[t];
    for (int tk = 0; tk < 16; tk++) {
        const int token = blockIdx.x * 16 + tk;
        __syncthreads();
        if (t < 8) sc[t] = g_scores[token*8 + t];
        __syncthreads();
        float4 w = ((const float4*)(g_wpre + (size_t)token * 1024))[t];
        float y0 = w.x, y1 = w.y, y2 = w.z, y3 = w.w;
        #pragma unroll
        for (int h = 0; h < 8; h++) {
            float s = sc[h];
            float4 bv = ((float4*)b2s)[h*256 + t];
            y0 += s*bv.x; y1 += s*bv.y; y2 += s*bv.z; y3 += s*bv.w;
        }
        float sum = y0 + y1 + y2 + y3;
        float sq  = y0*y0 + y1*y1 + y2*y2 + y3*y3;
        #pragma unroll
        for (int o = 16; o; o >>= 1) {
            sum += __shfl_xor_sync(0xffffffffu, sum, o);
            sq  += __shfl_xor_sync(0xffffffffu, sq, o);
        }
        const int wid = t >> 5;
        if ((t & 31) == 0) { rs[wid] = sum; rq[wid] = sq; }
        __syncthreads();
        float ts = 0.f, tq = 0.f;
        #pragma unroll
        for (int i = 0; i < 8; i++) { ts += rs[i]; tq += rq[i]; }
        const float m = ts * (1.f/1024.f);
        const float inv = rsqrtf(tq * (1.f/1024.f) - m*m + 1e-5f);
        float4 o;
        o.x = (y0-m)*inv*lg.x + lb.x;
        o.y = (y1-m)*inv*lg.y + lb.y;
        o.z = (y2-m)*inv*lg.z + lb.z;
        o.w = (y3-m)*inv*lg.w + lb.w;
        ((float4*)(out + (size_t)token * 1024))[t] = o;
    }
}

// ---------------- launch --------------------------------------------------
extern "C" void kernel_launch(void* const* d_in, const int* in_sizes, int n_in,
                              void* d_out, int out_size)
{
    const float* x     = (const float*)d_in[0];
    const float* W_ez  = (const float*)d_in[1];
    const float* b_ez  = (const float*)d_in[2];
    const float* U_h   = (const float*)d_in[3];
    const float* U_z   = (const float*)d_in[4];
    const float* b_u   = (const float*)d_in[5];
    const float* osh   = (const float*)d_in[6];
    const float* lns_g = (const float*)d_in[7];
    const float* lns_b = (const float*)d_in[8];
    const float* ffg   = (const float*)d_in[9];
    const float* ffb   = (const float*)d_in[10];
    const float* W1    = (const float*)d_in[11];
    const float* b1    = (const float*)d_in[12];
    const float* W2    = (const float*)d_in[13];
    const float* b2    = (const float*)d_in[14];
    const float* watt  = (const float*)d_in[15];
    const float* batt  = (const float*)d_in[16];
    const float* lno_g = (const float*)d_in[17];
    const float* lno_b = (const float*)d_in[18];
    float* out = (float*)d_out;

    float *gz, *gh1, *gwpre, *gxr, *gwezr, *gw2r;
    cudaGetSymbolAddress((void**)&gz,    g_z);
    cudaGetSymbolAddress((void**)&gh1,   g_h1);
    cudaGetSymbolAddress((void**)&gwpre, g_wpre);
    cudaGetSymbolAddress((void**)&gxr,   g_xr);
    cudaGetSymbolAddress((void**)&gwezr, g_wezr);
    cudaGetSymbolAddress((void**)&gw2r,  g_w2r);

    cudaFuncSetAttribute(gemm_tf32<1>, cudaFuncAttributeMaxDynamicSharedMemorySize, GEMM_SMEM_BYTES);
    cudaFuncSetAttribute(gemm_tf32<0>, cudaFuncAttributeMaxDynamicSharedMemorySize, GEMM_SMEM_BYTES);

    // pre-round operands to tf32 (unbiased RNA) so cp.async raw copies are exact
    round_tf32_kernel<<<8192, 256>>>((const float4*)x,    (float4*)gxr,   TOKENS*EMB/4);
    round_tf32_kernel<<<1024, 256>>>((const float4*)W_ez, (float4*)gwezr, EMB*HD/4);
    round_tf32_kernel<<<1024, 256>>>((const float4*)W2,   (float4*)gw2r,  HD*EMB/4);

    prep_kernel<<<130, 256>>>(W2, b2, watt, osh);

    dim3 gg(8, 64);  // (N/128, M/128)
    gemm_tf32<1><<<gg, 256, GEMM_SMEM_BYTES>>>(gxr, gwezr, b_ez, gz);

    scan_kernel<<<32, 32>>>(U_h, U_z, b_u, lns_g, lns_b);

    hln_kernel<<<8192, 256>>>(ffg, ffb);

    dim3 gf(64, 8);  // (M/128, heads)
    ffn1_kernel<<<gf, 256>>>(W1, b1, batt);

    softscale_kernel<<<8192, 128>>>();

    gemm_tf32<0><<<gg, 256, GEMM_SMEM_BYTES>>>(gh1, gw2r, nullptr, gwpre);

    final_kernel<<<512, 256>>>(b2, lno_g, lno_b, out);
}

// round 5
// speedup vs baseline: 1.4754x; 1.0301x over previous
#include <cuda_runtime.h>
#include <math.h>
#include <stdint.h>

#define TOKENS 8192      // B*S
#define EMB    1024      // E
#define HD     1024      // H*D
#define HEADS  8
#define DIM    128
#define SEQ    2048
#define BATCH  4

// ---------------- scratch (static device globals: allocation-free) ----------
__device__ float g_z[TOKENS*HD];
__device__ float g_hln[TOKENS*HD];     // tf32-rounded, written by scan
__device__ float g_h1[TOKENS*HD];
__device__ float g_wpre[TOKENS*EMB];
__device__ float g_xr[TOKENS*EMB];     // tf32-rounded x
__device__ float g_wezr[EMB*HD];       // tf32-rounded W_ez
__device__ float g_w2r[HD*EMB];        // tf32-rounded W2
__device__ float g_w1r[HD*DIM];        // tf32-rounded W1 (8*128*128)
__device__ float g_logits[TOKENS*HEADS];
__device__ float g_scores[TOKENS*HEADS];
__device__ float g_v[HD];        // v_h[d] = sum_e W2[h,d,e]*w_att[e]
__device__ float g_c[HEADS];     // c_h    = sum_e b2[h,e]*w_att[e]
__device__ float g_osd[HD];      // diag of out_shaper

// ---------------- helpers ---------------------------------------------------
__device__ __forceinline__ float round_tf32f(float x) {
    uint32_t r;
    asm("cvt.rna.tf32.f32 %0, %1;" : "=r"(r) : "f"(x));
    return __uint_as_float(r);
}
__device__ __forceinline__ uint32_t smem_u32(const void* p) {
    return (uint32_t)__cvta_generic_to_shared(p);
}
__device__ __forceinline__ void cp16(uint32_t s, const void* g) {
    asm volatile("cp.async.ca.shared.global [%0], [%1], 16;\n" :: "r"(s), "l"(g));
}
__device__ __forceinline__ float warp_sum(float v) {
    #pragma unroll
    for (int o = 16; o; o >>= 1) v += __shfl_xor_sync(0xffffffffu, v, o);
    return v;
}
__device__ __forceinline__ int redux_s32(int v) {
    int r;
    asm("redux.sync.add.s32 %0, %1, 0xffffffff;" : "=r"(r) : "r"(v));
    return r;
}
__device__ __forceinline__ void mma_tf32(float* c, const uint32_t* a, const uint32_t* b) {
    asm volatile(
        "mma.sync.aligned.m16n8k8.row.col.f32.tf32.tf32.f32 "
        "{%0,%1,%2,%3}, {%4,%5,%6,%7}, {%8,%9}, {%0,%1,%2,%3};\n"
        : "+f"(c[0]), "+f"(c[1]), "+f"(c[2]), "+f"(c[3])
        : "r"(a[0]), "r"(a[1]), "r"(a[2]), "r"(a[3]), "r"(b[0]), "r"(b[1]));
}

// ---------------- K-1: round fp32 -> tf32 (elementwise) ---------------------
__global__ void round_tf32_kernel(const float4* __restrict__ in, float4* __restrict__ out, int n4)
{
    int i = blockIdx.x * blockDim.x + threadIdx.x;
    if (i < n4) {
        float4 v = in[i];
        v.x = round_tf32f(v.x); v.y = round_tf32f(v.y);
        v.z = round_tf32f(v.z); v.w = round_tf32f(v.w);
        out[i] = v;
    }
}

// ---------------- K0: precompute v, c, out_shaper diag ----------------------
__global__ void prep_kernel(const float* __restrict__ W2, const float* __restrict__ b2,
                            const float* __restrict__ watt, const float* __restrict__ osh)
{
    const int wid  = blockIdx.x * 8 + (threadIdx.x >> 5);
    const int lane = threadIdx.x & 31;
    if (wid < 1024) {
        const float* p = W2 + (size_t)wid * 1024;
        float s = 0.f;
        for (int e = lane; e < 1024; e += 32) s += p[e] * watt[e];
        s = warp_sum(s);
        if (lane == 0) g_v[wid] = s;
    } else if (wid < 1032) {
        const int h = wid - 1024;
        const float* p = b2 + (size_t)h * 1024;
        float s = 0.f;
        for (int e = lane; e < 1024; e += 32) s += p[e] * watt[e];
        s = warp_sum(s);
        if (lane == 0) g_c[h] = s;
    } else if (wid < 1040) {
        const int i0 = (wid - 1032) * 32 + lane;   // 0..255
        #pragma unroll
        for (int r = 0; r < 4; r++) {
            int j = i0 + r * 256;                  // 0..1023
            g_osd[j] = osh[(j >> 7) * 16384 + (j & 127) * 129];
        }
    }
}

// ---------------- tf32 tensor-core GEMM: 8192 x 1024 x 1024 -----------------
// ACT==1: C = tanh(A@B + bias)   ACT==0: C = A@B
// 3-stage cp.async pipeline, conflict-free pitches (36 / 136).
#define AS_PITCH 36
#define BS_PITCH 136
#define AS_FLOATS (128*AS_PITCH)        // 4608
#define BS_FLOATS (32*BS_PITCH)         // 4352
#define GEMM_SMEM_BYTES ((3*AS_FLOATS + 3*BS_FLOATS) * 4)   // 107520

#define LOAD_TILE(buf, kb)                                                     \
    {                                                                          \
        float* Asb = dsm + (buf) * AS_FLOATS;                                  \
        float* Bsb = dsm + 3 * AS_FLOATS + (buf) * BS_FLOATS;                  \
        _Pragma("unroll")                                                      \
        for (int p = 0; p < 4; p++) {                                          \
            int idx = t + p * 256;                                             \
            int r  = idx >> 3, c  = (idx & 7) * 4;                             \
            cp16(smem_u32(Asb + r * AS_PITCH + c),                             \
                 A + (size_t)(m0 + r) * 1024 + (kb) + c);                      \
            int r2 = idx >> 5, c2 = (idx & 31) * 4;                            \
            cp16(smem_u32(Bsb + r2 * BS_PITCH + c2),                           \
                 Bm + (size_t)((kb) + r2) * 1024 + n0 + c2);                   \
        }                                                                      \
        asm volatile("cp.async.commit_group;\n");                              \
    }

template<int ACT>
__global__ __launch_bounds__(256)
void gemm_tf32(const float* __restrict__ A, const float* __restrict__ Bm,
               const float* __restrict__ bias, float* __restrict__ C)
{
    extern __shared__ float dsm[];
    const int t = threadIdx.x;
    const int m0 = blockIdx.y * 128, n0 = blockIdx.x * 128;
    const int lane = t & 31, wid = t >> 5;
    const int gid = lane >> 2, tig = lane & 3;
    const int mrow = (wid >> 1) * 32, ncol = (wid & 1) * 64;

    float acc[2][8][4];
    #pragma unroll
    for (int mi = 0; mi < 2; mi++)
        #pragma unroll
        for (int ni = 0; ni < 8; ni++)
            #pragma unroll
            for (int q = 0; q < 4; q++) acc[mi][ni][q] = 0.f;

    LOAD_TILE(0, 0);
    LOAD_TILE(1, 32);
    LOAD_TILE(2, 64);

    const int NT = 32;   // 1024/32 K-tiles
    for (int kt = 0; kt < NT; kt++) {
        const int buf = kt % 3;
        if (kt < NT - 2) { asm volatile("cp.async.wait_group 2;\n"); }
        else             { asm volatile("cp.async.wait_group 0;\n"); }
        __syncthreads();

        const uint32_t* As32 = (const uint32_t*)(dsm + buf * AS_FLOATS);
        const uint32_t* Bs32 = (const uint32_t*)(dsm + 3 * AS_FLOATS + buf * BS_FLOATS);
        #pragma unroll
        for (int kf = 0; kf < 4; kf++) {
            const int k8 = kf * 8;
            uint32_t a[2][4], b[8][2];
            #pragma unroll
            for (int mi = 0; mi < 2; mi++) {
                const uint32_t* ap = As32 + (mrow + mi * 16 + gid) * AS_PITCH + k8 + tig;
                a[mi][0] = ap[0];
                a[mi][1] = ap[8 * AS_PITCH];
                a[mi][2] = ap[4];
                a[mi][3] = ap[8 * AS_PITCH + 4];
            }
            #pragma unroll
            for (int ni = 0; ni < 8; ni++) {
                const uint32_t* bp = Bs32 + (k8 + tig) * BS_PITCH + ncol + ni * 8 + gid;
                b[ni][0] = bp[0];
                b[ni][1] = bp[4 * BS_PITCH];
            }
            #pragma unroll
            for (int mi = 0; mi < 2; mi++)
                #pragma unroll
                for (int ni = 0; ni < 8; ni++)
                    mma_tf32(acc[mi][ni], a[mi], b[ni]);
        }
        __syncthreads();
        if (kt + 3 < NT) { LOAD_TILE(buf, (kt + 3) * 32); }
    }

    // epilogue
    #pragma unroll
    for (int mi = 0; mi < 2; mi++) {
        const int row = m0 + mrow + mi * 16 + gid;
        #pragma unroll
        for (int ni = 0; ni < 8; ni++) {
            const int col = n0 + ncol + ni * 8 + 2 * tig;
            float v0 = acc[mi][ni][0], v1 = acc[mi][ni][1];
            float v2 = acc[mi][ni][2], v3 = acc[mi][ni][3];
            if (ACT == 1) {
                const float b0 = bias[col], b1 = bias[col + 1];
                v0 = tanhf(v0 + b0); v1 = tanhf(v1 + b1);
                v2 = tanhf(v2 + b0); v3 = tanhf(v3 + b1);
            }
            *(float2*)(C + (size_t)row * 1024 + col)       = make_float2(v0, v1);
            *(float2*)(C + (size_t)(row + 8) * 1024 + col) = make_float2(v2, v3);
        }
    }
}

// ---------------- scan (+fused per-head LN): one warp per (b,h) -------------
// step LN + hln LN reductions via redux.sync.add.s32 on fixed-point sums.
#define SUM_SC  1048576.f      // 2^20  (|sum| < 2048)
#define SUM_IS  (1.f/1048576.f)
#define SQ_SC   131072.f       // 2^17  (sq < 16384)
#define SQ_IS   (1.f/131072.f)
#define S2_SC   2097152.f      // 2^21
#define S2_IS   (1.f/2097152.f)
#define Q2_SC   524288.f       // 2^19
#define Q2_IS   (1.f/524288.f)

__global__ void scan_kernel(const float* __restrict__ Uh, const float* __restrict__ Uz,
                            const float* __restrict__ bu, const float* __restrict__ lg,
                            const float* __restrict__ lb, const float* __restrict__ fg,
                            const float* __restrict__ fb)
{
    const int seq  = blockIdx.x;         // 0..31
    const int lane = threadIdx.x;        // 0..31
    const int b = seq >> 3, h = seq & 7;
    const int d0 = lane * 4;
    float uh[4], uz[4], bb[4], gg[4], be[4], od[4], fgv[4], fbv[4];
    #pragma unroll
    for (int i = 0; i < 4; i++) {
        int d = d0 + i;
        uh[i]  = Uh[h*16384 + d*129];     // diagonal element
        uz[i]  = Uz[h*16384 + d*129];
        bb[i]  = bu[h*128 + d];
        gg[i]  = lg[d];
        be[i]  = lb[d];
        od[i]  = g_osd[h*128 + d];
        fgv[i] = fg[h*128 + d];
        fbv[i] = fb[h*128 + d];
    }
    const size_t base = (size_t)b * SEQ * HD + h * 128 + d0;
    const float4* zp = (const float4*)(g_z + base);
    float4* yp = (float4*)(g_hln + base);
    float hp[4] = {0.f, 0.f, 0.f, 0.f};
    float4 zc = zp[0];
    for (int s = 0; s < SEQ; s++) {
        float4 zn = make_float4(0.f, 0.f, 0.f, 0.f);
        if (s + 1 < SEQ) zn = zp[(size_t)(s + 1) * 256];
        float zt[4] = {zc.x, zc.y, zc.z, zc.w};
        float hn[4];
        #pragma unroll
        for (int i = 0; i < 4; i++) {
            float a = hp[i]*uh[i] + zt[i]*uz[i] + bb[i];
            float u = __fdividef(1.f, 1.f + __expf(-a));
            hn[i] = u*hp[i] + (1.f - u)*zt[i];
        }
        float vs = (hn[0]+hn[1]) + (hn[2]+hn[3]);
        float vq = (hn[0]*hn[0]+hn[1]*hn[1]) + (hn[2]*hn[2]+hn[3]*hn[3]);
        int si = redux_s32(__float2int_rn(vs * SUM_SC));
        int qi = redux_s32(__float2int_rn(vq * SQ_SC));
        float m   = (float)si * (SUM_IS/128.f);
        float msq = (float)qi * (SQ_IS/128.f);
        float inv = rsqrtf(msq - m*m + 1e-5f);
        #pragma unroll
        for (int i = 0; i < 4; i++) hp[i] = (hn[i]-m)*inv*gg[i] + be[i];

        // fused hln: shaped = hp*osd, per-head LN, tf32 round, store
        float sh[4];
        #pragma unroll
        for (int i = 0; i < 4; i++) sh[i] = hp[i]*od[i];
        float s2 = (sh[0]+sh[1]) + (sh[2]+sh[3]);
        float q2 = (sh[0]*sh[0]+sh[1]*sh[1]) + (sh[2]*sh[2]+sh[3]*sh[3]);
        int si2 = redux_s32(__float2int_rn(s2 * S2_SC));
        int qi2 = redux_s32(__float2int_rn(q2 * Q2_SC));
        float m2   = (float)si2 * (S2_IS/128.f);
        float mq2  = (float)qi2 * (Q2_IS/128.f);
        float inv2 = rsqrtf(mq2 - m2*m2 + 1e-5f);
        float4 y;
        y.x = round_tf32f((sh[0]-m2)*inv2*fgv[0] + fbv[0]);
        y.y = round_tf32f((sh[1]-m2)*inv2*fgv[1] + fbv[1]);
        y.z = round_tf32f((sh[2]-m2)*inv2*fgv[2] + fbv[2]);
        y.w = round_tf32f((sh[3]-m2)*inv2*fgv[3] + fbv[3]);
        yp[(size_t)s * 256] = y;
        zc = zn;
    }
}

// ---------------- K3b: per-head tf32 MMA GEMM + GELU + logits ---------------
// h1[t,h,:] = gelu(hln[t,h,:] @ W1[h] + b1[h]); logit[t,h] = h1·v_h + c_h + b_att
#define FAS_FLOATS (128*AS_PITCH)    // 4608
#define FBS_FLOATS (32*BS_PITCH)     // 4352
#define FFN_SMEM_BYTES ((2*FAS_FLOATS + 2*FBS_FLOATS) * 4)   // 71680

#define LOAD_FTILE(buf, kb)                                                    \
    {                                                                          \
        float* Asb = dsm + (buf) * FAS_FLOATS;                                 \
        float* Bsb = dsm + 2 * FAS_FLOATS + (buf) * FBS_FLOATS;                \
        _Pragma("unroll")                                                      \
        for (int p = 0; p < 4; p++) {                                          \
            int idx = t + p * 256;                                             \
            int r  = idx >> 3, c  = (idx & 7) * 4;                             \
            cp16(smem_u32(Asb + r * AS_PITCH + c),                             \
                 Abase + (size_t)r * 1024 + (kb) + c);                         \
            int r2 = idx >> 5, c2 = (idx & 31) * 4;                            \
            cp16(smem_u32(Bsb + r2 * BS_PITCH + c2),                           \
                 Bbase + ((kb) + r2) * 128 + c2);                              \
        }                                                                      \
        asm volatile("cp.async.commit_group;\n");                              \
    }

__global__ __launch_bounds__(256)
void ffn1_kernel(const float* __restrict__ W1r, const float* __restrict__ b1,
                 const float* __restrict__ batt)
{
    extern __shared__ float dsm[];
    __shared__ float red[128*9];
    const int t = threadIdx.x;
    const int m0 = blockIdx.x * 128;
    const int h  = blockIdx.y;
    const int lane = t & 31, wid = t >> 5;
    const int gid = lane >> 2, tig = lane & 3;
    const int mrow = (wid >> 1) * 32, ncol = (wid & 1) * 64;
    const float* Abase = g_hln + (size_t)m0 * 1024 + h * 128;
    const float* Bbase = W1r + h * 16384;

    float acc[2][8][4];
    #pragma unroll
    for (int mi = 0; mi < 2; mi++)
        #pragma unroll
        for (int ni = 0; ni < 8; ni++)
            #pragma unroll
            for (int q = 0; q < 4; q++) acc[mi][ni][q] = 0.f;

    LOAD_FTILE(0, 0);
    LOAD_FTILE(1, 32);

    const int NT = 4;   // 128/32
    for (int kt = 0; kt < NT; kt++) {
        const int buf = kt & 1;
        if (kt + 1 < NT) { asm volatile("cp.async.wait_group 1;\n"); }
        else             { asm volatile("cp.async.wait_group 0;\n"); }
        __syncthreads();

        const uint32_t* As32 = (const uint32_t*)(dsm + buf * FAS_FLOATS);
        const uint32_t* Bs32 = (const uint32_t*)(dsm + 2 * FAS_FLOATS + buf * FBS_FLOATS);
        #pragma unroll
        for (int kf = 0; kf < 4; kf++) {
            const int k8 = kf * 8;
            uint32_t a[2][4], b[8][2];
            #pragma unroll
            for (int mi = 0; mi < 2; mi++) {
                const uint32_t* ap = As32 + (mrow + mi * 16 + gid) * AS_PITCH + k8 + tig;
                a[mi][0] = ap[0];
                a[mi][1] = ap[8 * AS_PITCH];
                a[mi][2] = ap[4];
                a[mi][3] = ap[8 * AS_PITCH + 4];
            }
            #pragma unroll
            for (int ni = 0; ni < 8; ni++) {
                const uint32_t* bp = Bs32 + (k8 + tig) * BS_PITCH + ncol + ni * 8 + gid;
                b[ni][0] = bp[0];
                b[ni][1] = bp[4 * BS_PITCH];
            }
            #pragma unroll
            for (int mi = 0; mi < 2; mi++)
                #pragma unroll
                for (int ni = 0; ni < 8; ni++)
                    mma_tf32(acc[mi][ni], a[mi], b[ni]);
        }
        __syncthreads();
        if (kt + 2 < NT) { LOAD_FTILE(buf, (kt + 2) * 32); }
    }

    // epilogue: bias + GELU + h1 store + per-row logit partials
    float bv[8][2], vv[8][2];
    #pragma unroll
    for (int ni = 0; ni < 8; ni++) {
        const int col = ncol + ni * 8 + 2 * tig;
        bv[ni][0] = b1[h*128 + col];     bv[ni][1] = b1[h*128 + col + 1];
        vv[ni][0] = g_v[h*128 + col];    vv[ni][1] = g_v[h*128 + col + 1];
    }
    const float cadd = g_c[h] + batt[0];
    #pragma unroll
    for (int mi = 0; mi < 2; mi++) {
        const int r1 = mrow + mi * 16 + gid;
        const int r2 = r1 + 8;
        float lp1 = 0.f, lp2 = 0.f;
        #pragma unroll
        for (int ni = 0; ni < 8; ni++) {
            const int col = ncol + ni * 8 + 2 * tig;
            float x0 = acc[mi][ni][0] + bv[ni][0];
            float x1 = acc[mi][ni][1] + bv[ni][1];
            float x2 = acc[mi][ni][2] + bv[ni][0];
            float x3 = acc[mi][ni][3] + bv[ni][1];
            float g0 = 0.5f * x0 * (1.f + erff(x0 * 0.70710678118654752f));
            float g1 = 0.5f * x1 * (1.f + erff(x1 * 0.70710678118654752f));
            float g2 = 0.5f * x2 * (1.f + erff(x2 * 0.70710678118654752f));
            float g3 = 0.5f * x3 * (1.f + erff(x3 * 0.70710678118654752f));
            lp1 += g0*vv[ni][0] + g1*vv[ni][1];
            lp2 += g2*vv[ni][0] + g3*vv[ni][1];
            *(float2*)(g_h1 + (size_t)(m0 + r1) * 1024 + h*128 + col) = make_float2(g0, g1);
            *(float2*)(g_h1 + (size_t)(m0 + r2) * 1024 + h*128 + col) = make_float2(g2, g3);
        }
        red[r1*9 + (wid & 1)*4 + tig] = lp1;
        red[r2*9 + (wid & 1)*4 + tig] = lp2;
    }
    __syncthreads();
    if (t < 128) {
        float s = 0.f;
        #pragma unroll
        for (int j = 0; j < 8; j++) s += red[t*9 + j];
        g_logits[(size_t)(m0 + t) * 8 + h] = s + cadd;
    }
}

// ---------------- K3c: softmax over heads, scale h1 (tf32-rounded) ----------
__global__ void softscale_kernel()
{
    const int tok = blockIdx.x;
    const int t = threadIdx.x;   // 128
    float l[8];
    #pragma unroll
    for (int h = 0; h < 8; h++) l[h] = g_logits[tok*8 + h];
    float mx = l[0];
    #pragma unroll
    for (int h = 1; h < 8; h++) mx = fmaxf(mx, l[h]);
    float e[8]; float s = 0.f;
    #pragma unroll
    for (int h = 0; h < 8; h++) { e[h] = __expf(l[h] - mx); s += e[h]; }
    const float inv = __fdividef(1.f, s);
    float p[8];
    #pragma unroll
    for (int h = 0; h < 8; h++) p[h] = e[h] * inv;
    const size_t base = (size_t)tok * HD;
    #pragma unroll
    for (int r = 0; r < 8; r++)
        g_h1[base + r*128 + t] = round_tf32f(g_h1[base + r*128 + t] * p[r]);
    if (t < 8) g_scores[tok*8 + t] = p[t];
}

// ---------------- K5: weighted = wpre + scores@b2, output LN ----------------
__global__ __launch_bounds__(256)
void final_kernel(const float* __restrict__ b2, const float* __restrict__ lno_g,
                  const float* __restrict__ lno_b, float* __restrict__ out)
{
    __shared__ float b2s[8192];
    __shared__ float sc[8];
    __shared__ float rs[8], rq[8];
    const int t = threadIdx.x;
    for (int i = t; i < 2048; i += 256)
        ((float4*)b2s)[i] = ((const float4*)b2)[i];
    float4 lg = ((const float4*)lno_g)[t];
    float4 lb = ((const float4*)lno_b)[t];
    for (int tk = 0; tk < 16; tk++) {
        const int token = blockIdx.x * 16 + tk;
        __syncthreads();
        if (t < 8) sc[t] = g_scores[token*8 + t];
        __syncthreads();
        float4 w = ((const float4*)(g_wpre + (size_t)token * 1024))[t];
        float y0 = w.x, y1 = w.y, y2 = w.z, y3 = w.w;
        #pragma unroll
        for (int h = 0; h < 8; h++) {
            float s = sc[h];
            float4 bvv = ((float4*)b2s)[h*256 + t];
            y0 += s*bvv.x; y1 += s*bvv.y; y2 += s*bvv.z; y3 += s*bvv.w;
        }
        float sum = y0 + y1 + y2 + y3;
        float sq  = y0*y0 + y1*y1 + y2*y2 + y3*y3;
        #pragma unroll
        for (int o = 16; o; o >>= 1) {
            sum += __shfl_xor_sync(0xffffffffu, sum, o);
            sq  += __shfl_xor_sync(0xffffffffu, sq, o);
        }
        const int wdx = t >> 5;
        if ((t & 31) == 0) { rs[wdx] = sum; rq[wdx] = sq; }
        __syncthreads();
        float ts = 0.f, tq = 0.f;
        #pragma unroll
        for (int i = 0; i < 8; i++) { ts += rs[i]; tq += rq[i]; }
        const float m = ts * (1.f/1024.f);
        const float inv = rsqrtf(tq * (1.f/1024.f) - m*m + 1e-5f);
        float4 o;
        o.x = (y0-m)*inv*lg.x + lb.x;
        o.y = (y1-m)*inv*lg.y + lb.y;
        o.z = (y2-m)*inv*lg.z + lb.z;
        o.w = (y3-m)*inv*lg.w + lb.w;
        ((float4*)(out + (size_t)token * 1024))[t] = o;
    }
}

// ---------------- launch --------------------------------------------------
extern "C" void kernel_launch(void* const* d_in, const int* in_sizes, int n_in,
                              void* d_out, int out_size)
{
    const float* x     = (const float*)d_in[0];
    const float* W_ez  = (const float*)d_in[1];
    const float* b_ez  = (const float*)d_in[2];
    const float* U_h   = (const float*)d_in[3];
    const float* U_z   = (const float*)d_in[4];
    const float* b_u   = (const float*)d_in[5];
    const float* osh   = (const float*)d_in[6];
    const float* lns_g = (const float*)d_in[7];
    const float* lns_b = (const float*)d_in[8];
    const float* ffg   = (const float*)d_in[9];
    const float* ffb   = (const float*)d_in[10];
    const float* W1    = (const float*)d_in[11];
    const float* b1    = (const float*)d_in[12];
    const float* W2    = (const float*)d_in[13];
    const float* b2    = (const float*)d_in[14];
    const float* watt  = (const float*)d_in[15];
    const float* batt  = (const float*)d_in[16];
    const float* lno_g = (const float*)d_in[17];
    const float* lno_b = (const float*)d_in[18];
    float* out = (float*)d_out;

    float *gz, *gh1, *gwpre, *gxr, *gwezr, *gw2r, *gw1r;
    cudaGetSymbolAddress((void**)&gz,    g_z);
    cudaGetSymbolAddress((void**)&gh1,   g_h1);
    cudaGetSymbolAddress((void**)&gwpre, g_wpre);
    cudaGetSymbolAddress((void**)&gxr,   g_xr);
    cudaGetSymbolAddress((void**)&gwezr, g_wezr);
    cudaGetSymbolAddress((void**)&gw2r,  g_w2r);
    cudaGetSymbolAddress((void**)&gw1r,  g_w1r);

    cudaFuncSetAttribute(gemm_tf32<1>, cudaFuncAttributeMaxDynamicSharedMemorySize, GEMM_SMEM_BYTES);
    cudaFuncSetAttribute(gemm_tf32<0>, cudaFuncAttributeMaxDynamicSharedMemorySize, GEMM_SMEM_BYTES);
    cudaFuncSetAttribute(ffn1_kernel,  cudaFuncAttributeMaxDynamicSharedMemorySize, FFN_SMEM_BYTES);

    // pre-round operands to tf32 (unbiased RNA) so cp.async raw copies are exact
    round_tf32_kernel<<<8192, 256>>>((const float4*)x,    (float4*)gxr,   TOKENS*EMB/4);
    round_tf32_kernel<<<1024, 256>>>((const float4*)W_ez, (float4*)gwezr, EMB*HD/4);
    round_tf32_kernel<<<1024, 256>>>((const float4*)W2,   (float4*)gw2r,  HD*EMB/4);
    round_tf32_kernel<<<128,  256>>>((const float4*)W1,   (float4*)gw1r,  HD*DIM/4);

    prep_kernel<<<130, 256>>>(W2, b2, watt, osh);

    dim3 gg(8, 64);  // (N/128, M/128)
    gemm_tf32<1><<<gg, 256, GEMM_SMEM_BYTES>>>(gxr, gwezr, b_ez, gz);

    scan_kernel<<<32, 32>>>(U_h, U_z, b_u, lns_g, lns_b, ffg, ffb);

    dim3 gf(64, 8);  // (M/128, heads)
    ffn1_kernel<<<gf, 256, FFN_SMEM_BYTES>>>(gw1r, b1, batt);

    softscale_kernel<<<8192, 128>>>();

    gemm_tf32<0><<<gg, 256, GEMM_SMEM_BYTES>>>(gh1, gw2r, nullptr, gwpre);

    final_kernel<<<512, 256>>>(b2, lno_g, lno_b, out);
}

// round 7
// speedup vs baseline: 2.0211x; 1.3699x over previous
#include <cuda_runtime.h>
#include <math.h>
#include <stdint.h>

#define TOKENS 8192      // B*S
#define EMB    1024      // E
#define HD     1024      // H*D
#define HEADS  8
#define DIM    128
#define SEQ    2048
#define BATCH  4

// ---------------- scratch (static device globals: allocation-free) ----------
__device__ float g_z[TOKENS*HD];
__device__ float g_hln[TOKENS*HD];     // tf32-rounded, written by scan
__device__ float g_h1[TOKENS*HD];
__device__ float g_wpre[TOKENS*EMB];
__device__ float g_wezr[EMB*HD];       // tf32-rounded W_ez
__device__ float g_w2r[HD*EMB];        // tf32-rounded W2
__device__ float g_w1r[HD*DIM];        // tf32-rounded W1 (8*128*128)
__device__ float g_logits[TOKENS*HEADS];
__device__ float g_scores[TOKENS*HEADS];
__device__ float g_v[HD];        // v_h[d] = sum_e W2[h,d,e]*w_att[e]
__device__ float g_c[HEADS];     // c_h    = sum_e b2[h,e]*w_att[e]
__device__ float g_osd[HD];      // diag of out_shaper

// ---------------- helpers ---------------------------------------------------
__device__ __forceinline__ float round_tf32f(float x) {
    uint32_t r;
    asm("cvt.rna.tf32.f32 %0, %1;" : "=r"(r) : "f"(x));
    return __uint_as_float(r);
}
__device__ __forceinline__ uint32_t round_tf32b(float x) {
    uint32_t r;
    asm("cvt.rna.tf32.f32 %0, %1;" : "=r"(r) : "f"(x));
    return r;
}
__device__ __forceinline__ uint32_t smem_u32(const void* p) {
    return (uint32_t)__cvta_generic_to_shared(p);
}
__device__ __forceinline__ void cp16(uint32_t s, const void* g) {
    asm volatile("cp.async.ca.shared.global [%0], [%1], 16;\n" :: "r"(s), "l"(g));
}
__device__ __forceinline__ float warp_sum(float v) {
    #pragma unroll
    for (int o = 16; o; o >>= 1) v += __shfl_xor_sync(0xffffffffu, v, o);
    return v;
}
__device__ __forceinline__ int redux_s32(int v) {
    int r;
    asm("redux.sync.add.s32 %0, %1, 0xffffffff;" : "=r"(r) : "r"(v));
    return r;
}
__device__ __forceinline__ void mma_tf32(float* c, const uint32_t* a, const uint32_t* b) {
    asm volatile(
        "mma.sync.aligned.m16n8k8.row.col.f32.tf32.tf32.f32 "
        "{%0,%1,%2,%3}, {%4,%5,%6,%7}, {%8,%9}, {%0,%1,%2,%3};\n"
        : "+f"(c[0]), "+f"(c[1]), "+f"(c[2]), "+f"(c[3])
        : "r"(a[0]), "r"(a[1]), "r"(a[2]), "r"(a[3]), "r"(b[0]), "r"(b[1]));
}

// ---------------- K-1: round fp32 -> tf32 (elementwise) ---------------------
__global__ void round_tf32_kernel(const float4* __restrict__ in, float4* __restrict__ out, int n4)
{
    int i = blockIdx.x * blockDim.x + threadIdx.x;
    if (i < n4) {
        float4 v = in[i];
        v.x = round_tf32f(v.x); v.y = round_tf32f(v.y);
        v.z = round_tf32f(v.z); v.w = round_tf32f(v.w);
        out[i] = v;
    }
}

// ---------------- K0: precompute v, c, out_shaper diag ----------------------
__global__ void prep_kernel(const float* __restrict__ W2, const float* __restrict__ b2,
                            const float* __restrict__ watt, const float* __restrict__ osh)
{
    const int wid  = blockIdx.x * 8 + (threadIdx.x >> 5);
    const int lane = threadIdx.x & 31;
    if (wid < 1024) {
        const float* p = W2 + (size_t)wid * 1024;
        float s = 0.f;
        for (int e = lane; e < 1024; e += 32) s += p[e] * watt[e];
        s = warp_sum(s);
        if (lane == 0) g_v[wid] = s;
    } else if (wid < 1032) {
        const int h = wid - 1024;
        const float* p = b2 + (size_t)h * 1024;
        float s = 0.f;
        for (int e = lane; e < 1024; e += 32) s += p[e] * watt[e];
        s = warp_sum(s);
        if (lane == 0) g_c[h] = s;
    } else if (wid < 1040) {
        const int i0 = (wid - 1032) * 32 + lane;   // 0..255
        #pragma unroll
        for (int r = 0; r < 4; r++) {
            int j = i0 + r * 256;                  // 0..1023
            g_osd[j] = osh[(j >> 7) * 16384 + (j & 127) * 129];
        }
    }
}

// ---------------- tf32 tensor-core GEMM: 8192 x 1024 x 1024 -----------------
// ACT==1: C = tanh(A@B + bias)   ACT==0: C = A@B
// ROUND_A==1: A is raw fp32; fragments are RNA-rounded to tf32 after LDS.
// 2-stage cp.async pipeline, conflict-free pitches (36 / 136), 3 CTAs/SM.
#define AS_PITCH 36
#define BS_PITCH 136
#define AS_FLOATS (128*AS_PITCH)        // 4608
#define BS_FLOATS (32*BS_PITCH)         // 4352
#define GEMM_SMEM_BYTES ((2*AS_FLOATS + 2*BS_FLOATS) * 4)   // 71680

#define LOAD_TILE(buf, kb)                                                     \
    {                                                                          \
        float* Asb = dsm + (buf) * AS_FLOATS;                                  \
        float* Bsb = dsm + 2 * AS_FLOATS + (buf) * BS_FLOATS;                  \
        _Pragma("unroll")                                                      \
        for (int p = 0; p < 4; p++) {                                          \
            int idx = t + p * 256;                                             \
            int r  = idx >> 3, c  = (idx & 7) * 4;                             \
            cp16(smem_u32(Asb + r * AS_PITCH + c),                             \
                 A + (size_t)(m0 + r) * 1024 + (kb) + c);                      \
            int r2 = idx >> 5, c2 = (idx & 31) * 4;                            \
            cp16(smem_u32(Bsb + r2 * BS_PITCH + c2),                           \
                 Bm + (size_t)((kb) + r2) * 1024 + n0 + c2);                   \
        }                                                                      \
        asm volatile("cp.async.commit_group;\n");                              \
    }

template<int ACT, int ROUND_A>
__global__ __launch_bounds__(256)
void gemm_tf32(const float* __restrict__ A, const float* __restrict__ Bm,
               const float* __restrict__ bias, float* __restrict__ C)
{
    extern __shared__ float dsm[];
    const int t = threadIdx.x;
    const int m0 = blockIdx.y * 128, n0 = blockIdx.x * 128;
    const int lane = t & 31, wid = t >> 5;
    const int gid = lane >> 2, tig = lane & 3;
    const int mrow = (wid >> 1) * 32, ncol = (wid & 1) * 64;

    float acc[2][8][4];
    #pragma unroll
    for (int mi = 0; mi < 2; mi++)
        #pragma unroll
        for (int ni = 0; ni < 8; ni++)
            #pragma unroll
            for (int q = 0; q < 4; q++) acc[mi][ni][q] = 0.f;

    LOAD_TILE(0, 0);
    LOAD_TILE(1, 32);

    const int NT = 32;   // 1024/32 K-tiles
    for (int kt = 0; kt < NT; kt++) {
        const int buf = kt & 1;
        if (kt + 1 < NT) { asm volatile("cp.async.wait_group 1;\n"); }
        else             { asm volatile("cp.async.wait_group 0;\n"); }
        __syncthreads();

        const uint32_t* As32 = (const uint32_t*)(dsm + buf * AS_FLOATS);
        const uint32_t* Bs32 = (const uint32_t*)(dsm + 2 * AS_FLOATS + buf * BS_FLOATS);
        #pragma unroll
        for (int kf = 0; kf < 4; kf++) {
            const int k8 = kf * 8;
            uint32_t a[2][4], b[8][2];
            #pragma unroll
            for (int mi = 0; mi < 2; mi++) {
                const uint32_t* ap = As32 + (mrow + mi * 16 + gid) * AS_PITCH + k8 + tig;
                a[mi][0] = ap[0];
                a[mi][1] = ap[8 * AS_PITCH];
                a[mi][2] = ap[4];
                a[mi][3] = ap[8 * AS_PITCH + 4];
                if (ROUND_A) {
                    #pragma unroll
                    for (int q = 0; q < 4; q++)
                        a[mi][q] = round_tf32b(__uint_as_float(a[mi][q]));
                }
            }
            #pragma unroll
            for (int ni = 0; ni < 8; ni++) {
                const uint32_t* bp = Bs32 + (k8 + tig) * BS_PITCH + ncol + ni * 8 + gid;
                b[ni][0] = bp[0];
                b[ni][1] = bp[4 * BS_PITCH];
            }
            #pragma unroll
            for (int mi = 0; mi < 2; mi++)
                #pragma unroll
                for (int ni = 0; ni < 8; ni++)
                    mma_tf32(acc[mi][ni], a[mi], b[ni]);
        }
        __syncthreads();
        if (kt + 2 < NT) { LOAD_TILE(buf, (kt + 2) * 32); }
    }

    // epilogue
    #pragma unroll
    for (int mi = 0; mi < 2; mi++) {
        const int row = m0 + mrow + mi * 16 + gid;
        #pragma unroll
        for (int ni = 0; ni < 8; ni++) {
            const int col = n0 + ncol + ni * 8 + 2 * tig;
            float v0 = acc[mi][ni][0], v1 = acc[mi][ni][1];
            float v2 = acc[mi][ni][2], v3 = acc[mi][ni][3];
            if (ACT == 1) {
                const float b0 = bias[col], b1 = bias[col + 1];
                v0 = tanhf(v0 + b0); v1 = tanhf(v1 + b1);
                v2 = tanhf(v2 + b0); v3 = tanhf(v3 + b1);
            }
            *(float2*)(C + (size_t)row * 1024 + col)       = make_float2(v0, v1);
            *(float2*)(C + (size_t)(row + 8) * 1024 + col) = make_float2(v2, v3);
        }
    }
}

// ---------------- scan (+fused per-head LN): one warp per (b,h) -------------
// cp.async ring prefetch (depth 16) hides z-load latency; LN reductions via
// redux.sync.add.s32 on fixed-point sums.
#define SUM_SC  1048576.f      // 2^20  (|sum| < 2048)
#define SUM_IS  (1.f/1048576.f)
#define SQ_SC   131072.f       // 2^17  (sq < 16384)
#define SQ_IS   (1.f/131072.f)
#define S2_SC   2097152.f      // 2^21
#define S2_IS   (1.f/2097152.f)
#define Q2_SC   524288.f       // 2^19
#define Q2_IS   (1.f/524288.f)
#define RSTAGE  16

__global__ void scan_kernel(const float* __restrict__ Uh, const float* __restrict__ Uz,
                            const float* __restrict__ bu, const float* __restrict__ lg,
                            const float* __restrict__ lb, const float* __restrict__ fg,
                            const float* __restrict__ fb)
{
    __shared__ float ring[RSTAGE * 128];
    const int seq  = blockIdx.x;         // 0..31
    const int lane = threadIdx.x;        // 0..31
    const int b = seq >> 3, h = seq & 7;
    const int d0 = lane * 4;
    float uh[4], uz[4], bb[4], gg[4], be[4], od[4], fgv[4], fbv[4];
    #pragma unroll
    for (int i = 0; i < 4; i++) {
        int d = d0 + i;
        uh[i]  = Uh[h*16384 + d*129];     // diagonal element
        uz[i]  = Uz[h*16384 + d*129];
        bb[i]  = bu[h*128 + d];
        gg[i]  = lg[d];
        be[i]  = lb[d];
        od[i]  = g_osd[h*128 + d];
        fgv[i] = fg[h*128 + d];
        fbv[i] = fb[h*128 + d];
    }
    const size_t base = (size_t)b * SEQ * HD + h * 128 + d0;
    const float* zg = g_z + (size_t)b * SEQ * HD + h * 128;   // + s*1024 + lane*4
    float4* yp = (float4*)(g_hln + base);
    const uint32_t myslot = smem_u32(ring) + lane * 16;

    // prefetch stages 0..RSTAGE-1, one commit group per stage
    #pragma unroll
    for (int p = 0; p < RSTAGE; p++) {
        cp16(myslot + p * 512, zg + (size_t)p * 1024 + lane * 4);
        asm volatile("cp.async.commit_group;\n");
    }

    float hp[4] = {0.f, 0.f, 0.f, 0.f};
    for (int s = 0; s < SEQ; s++) {
        const int nxt = s + RSTAGE;
        if (nxt < SEQ)
            cp16(myslot + (nxt & (RSTAGE-1)) * 512, zg + (size_t)nxt * 1024 + lane * 4);
        asm volatile("cp.async.commit_group;\n");
        // allow the newest RSTAGE groups in flight -> stage s complete
        asm volatile("cp.async.wait_group %0;\n" :: "n"(RSTAGE));

        float4 zc = *(const float4*)(ring + (s & (RSTAGE-1)) * 128 + d0);
        float zt[4] = {zc.x, zc.y, zc.z, zc.w};
        float hn[4];
        #pragma unroll
        for (int i = 0; i < 4; i++) {
            float a = hp[i]*uh[i] + zt[i]*uz[i] + bb[i];
            float u = __fdividef(1.f, 1.f + __expf(-a));
            hn[i] = u*hp[i] + (1.f - u)*zt[i];
        }
        float vs = (hn[0]+hn[1]) + (hn[2]+hn[3]);
        float vq = (hn[0]*hn[0]+hn[1]*hn[1]) + (hn[2]*hn[2]+hn[3]*hn[3]);
        int si = redux_s32(__float2int_rn(vs * SUM_SC));
        int qi = redux_s32(__float2int_rn(vq * SQ_SC));
        float m   = (float)si * (SUM_IS/128.f);
        float msq = (float)qi * (SQ_IS/128.f);
        float inv = rsqrtf(msq - m*m + 1e-5f);
        #pragma unroll
        for (int i = 0; i < 4; i++) hp[i] = (hn[i]-m)*inv*gg[i] + be[i];

        // fused hln: shaped = hp*osd, per-head LN, tf32 round, store
        float sh[4];
        #pragma unroll
        for (int i = 0; i < 4; i++) sh[i] = hp[i]*od[i];
        float s2 = (sh[0]+sh[1]) + (sh[2]+sh[3]);
        float q2 = (sh[0]*sh[0]+sh[1]*sh[1]) + (sh[2]*sh[2]+sh[3]*sh[3]);
        int si2 = redux_s32(__float2int_rn(s2 * S2_SC));
        int qi2 = redux_s32(__float2int_rn(q2 * Q2_SC));
        float m2   = (float)si2 * (S2_IS/128.f);
        float mq2  = (float)qi2 * (Q2_IS/128.f);
        float inv2 = rsqrtf(mq2 - m2*m2 + 1e-5f);
        float4 y;
        y.x = round_tf32f((sh[0]-m2)*inv2*fgv[0] + fbv[0]);
        y.y = round_tf32f((sh[1]-m2)*inv2*fgv[1] + fbv[1]);
        y.z = round_tf32f((sh[2]-m2)*inv2*fgv[2] + fbv[2]);
        y.w = round_tf32f((sh[3]-m2)*inv2*fgv[3] + fbv[3]);
        yp[(size_t)s * 256] = y;
    }
}

// ---------------- K3b: per-head tf32 MMA GEMM + GELU + logits ---------------
#define FAS_FLOATS (128*AS_PITCH)    // 4608
#define FBS_FLOATS (32*BS_PITCH)     // 4352
#define FFN_SMEM_BYTES ((2*FAS_FLOATS + 2*FBS_FLOATS) * 4)   // 71680

#define LOAD_FTILE(buf, kb)                                                    \
    {                                                                          \
        float* Asb = dsm + (buf) * FAS_FLOATS;                                 \
        float* Bsb = dsm + 2 * FAS_FLOATS + (buf) * FBS_FLOATS;                \
        _Pragma("unroll")                                                      \
        for (int p = 0; p < 4; p++) {                                          \
            int idx = t + p * 256;                                             \
            int r  = idx >> 3, c  = (idx & 7) * 4;                             \
            cp16(smem_u32(Asb + r * AS_PITCH + c),                             \
                 Abase + (size_t)r * 1024 + (kb) + c);                         \
            int r2 = idx >> 5, c2 = (idx & 31) * 4;                            \
            cp16(smem_u32(Bsb + r2 * BS_PITCH + c2),                           \
                 Bbase + ((kb) + r2) * 128 + c2);                              \
        }                                                                      \
        asm volatile("cp.async.commit_group;\n");                              \
    }

__global__ __launch_bounds__(256)
void ffn1_kernel(const float* __restrict__ W1r, const float* __restrict__ b1,
                 const float* __restrict__ batt)
{
    extern __shared__ float dsm[];
    __shared__ float red[128*9];
    const int t = threadIdx.x;
    const int m0 = blockIdx.x * 128;
    const int h  = blockIdx.y;
    const int lane = t & 31, wid = t >> 5;
    const int gid = lane >> 2, tig = lane & 3;
    const int mrow = (wid >> 1) * 32, ncol = (wid & 1) * 64;
    const float* Abase = g_hln + (size_t)m0 * 1024 + h * 128;
    const float* Bbase = W1r + h * 16384;

    float acc[2][8][4];
    #pragma unroll
    for (int mi = 0; mi < 2; mi++)
        #pragma unroll
        for (int ni = 0; ni < 8; ni++)
            #pragma unroll
            for (int q = 0; q < 4; q++) acc[mi][ni][q] = 0.f;

    LOAD_FTILE(0, 0);
    LOAD_FTILE(1, 32);

    const int NT = 4;   // 128/32
    for (int kt = 0; kt < NT; kt++) {
        const int buf = kt & 1;
        if (kt + 1 < NT) { asm volatile("cp.async.wait_group 1;\n"); }
        else             { asm volatile("cp.async.wait_group 0;\n"); }
        __syncthreads();

        const uint32_t* As32 = (const uint32_t*)(dsm + buf * FAS_FLOATS);
        const uint32_t* Bs32 = (const uint32_t*)(dsm + 2 * FAS_FLOATS + buf * FBS_FLOATS);
        #pragma unroll
        for (int kf = 0; kf < 4; kf++) {
            const int k8 = kf * 8;
            uint32_t a[2][4], b[8][2];
            #pragma unroll
            for (int mi = 0; mi < 2; mi++) {
                const uint32_t* ap = As32 + (mrow + mi * 16 + gid) * AS_PITCH + k8 + tig;
                a[mi][0] = ap[0];
                a[mi][1] = ap[8 * AS_PITCH];
                a[mi][2] = ap[4];
                a[mi][3] = ap[8 * AS_PITCH + 4];
            }
            #pragma unroll
            for (int ni = 0; ni < 8; ni++) {
                const uint32_t* bp = Bs32 + (k8 + tig) * BS_PITCH + ncol + ni * 8 + gid;
                b[ni][0] = bp[0];
                b[ni][1] = bp[4 * BS_PITCH];
            }
            #pragma unroll
            for (int mi = 0; mi < 2; mi++)
                #pragma unroll
                for (int ni = 0; ni < 8; ni++)
                    mma_tf32(acc[mi][ni], a[mi], b[ni]);
        }
        __syncthreads();
        if (kt + 2 < NT) { LOAD_FTILE(buf, (kt + 2) * 32); }
    }

    // epilogue: bias + GELU + h1 store + per-row logit partials
    float bv[8][2], vv[8][2];
    #pragma unroll
    for (int ni = 0; ni < 8; ni++) {
        const int col = ncol + ni * 8 + 2 * tig;
        bv[ni][0] = b1[h*128 + col];     bv[ni][1] = b1[h*128 + col + 1];
        vv[ni][0] = g_v[h*128 + col];    vv[ni][1] = g_v[h*128 + col + 1];
    }
    const float cadd = g_c[h] + batt[0];
    #pragma unroll
    for (int mi = 0; mi < 2; mi++) {
        const int r1 = mrow + mi * 16 + gid;
        const int r2 = r1 + 8;
        float lp1 = 0.f, lp2 = 0.f;
        #pragma unroll
        for (int ni = 0; ni < 8; ni++) {
            const int col = ncol + ni * 8 + 2 * tig;
            float x0 = acc[mi][ni][0] + bv[ni][0];
            float x1 = acc[mi][ni][1] + bv[ni][1];
            float x2 = acc[mi][ni][2] + bv[ni][0];
            float x3 = acc[mi][ni][3] + bv[ni][1];
            float g0 = 0.5f * x0 * (1.f + erff(x0 * 0.70710678118654752f));
            float g1 = 0.5f * x1 * (1.f + erff(x1 * 0.70710678118654752f));
            float g2 = 0.5f * x2 * (1.f + erff(x2 * 0.70710678118654752f));
            float g3 = 0.5f * x3 * (1.f + erff(x3 * 0.70710678118654752f));
            lp1 += g0*vv[ni][0] + g1*vv[ni][1];
            lp2 += g2*vv[ni][0] + g3*vv[ni][1];
            *(float2*)(g_h1 + (size_t)(m0 + r1) * 1024 + h*128 + col) = make_float2(g0, g1);
            *(float2*)(g_h1 + (size_t)(m0 + r2) * 1024 + h*128 + col) = make_float2(g2, g3);
        }
        red[r1*9 + (wid & 1)*4 + tig] = lp1;
        red[r2*9 + (wid & 1)*4 + tig] = lp2;
    }
    __syncthreads();
    if (t < 128) {
        float s = 0.f;
        #pragma unroll
        for (int j = 0; j < 8; j++) s += red[t*9 + j];
        g_logits[(size_t)(m0 + t) * 8 + h] = s + cadd;
    }
}

// ---------------- K3c: softmax over heads, scale h1 (tf32-rounded) ----------
__global__ void softscale_kernel()
{
    const int tok = blockIdx.x;
    const int t = threadIdx.x;   // 128
    float l[8];
    #pragma unroll
    for (int h = 0; h < 8; h++) l[h] = g_logits[tok*8 + h];
    float mx = l[0];
    #pragma unroll
    for (int h = 1; h < 8; h++) mx = fmaxf(mx, l[h]);
    float e[8]; float s = 0.f;
    #pragma unroll
    for (int h = 0; h < 8; h++) { e[h] = __expf(l[h] - mx); s += e[h]; }
    const float inv = __fdividef(1.f, s);
    float p[8];
    #pragma unroll
    for (int h = 0; h < 8; h++) p[h] = e[h] * inv;
    const size_t base = (size_t)tok * HD;
    #pragma unroll
    for (int r = 0; r < 8; r++)
        g_h1[base + r*128 + t] = round_tf32f(g_h1[base + r*128 + t] * p[r]);
    if (t < 8) g_scores[tok*8 + t] = p[t];
}

// ---------------- K5: weighted = wpre + scores@b2, output LN ----------------
__global__ __launch_bounds__(256)
void final_kernel(const float* __restrict__ b2, const float* __restrict__ lno_g,
                  const float* __restrict__ lno_b, float* __restrict__ out)
{
    __shared__ float b2s[8192];
    __shared__ float sc[8];
    __shared__ float rs[8], rq[8];
    const int t = threadIdx.x;
    for (int i = t; i < 2048; i += 256)
        ((float4*)b2s)[i] = ((const float4*)b2)[i];
    float4 lg = ((const float4*)lno_g)[t];
    float4 lb = ((const float4*)lno_b)[t];
    for (int tk = 0; tk < 16; tk++) {
        const int token = blockIdx.x * 16 + tk;
        __syncthreads();
        if (t < 8) sc[t] = g_scores[token*8 + t];
        __syncthreads();
        float4 w = ((const float4*)(g_wpre + (size_t)token * 1024))[t];
        float y0 = w.x, y1 = w.y, y2 = w.z, y3 = w.w;
        #pragma unroll
        for (int h = 0; h < 8; h++) {
            float s = sc[h];
            float4 bvv = ((float4*)b2s)[h*256 + t];
            y0 += s*bvv.x; y1 += s*bvv.y; y2 += s*bvv.z; y3 += s*bvv.w;
        }
        float sum = y0 + y1 + y2 + y3;
        float sq  = y0*y0 + y1*y1 + y2*y2 + y3*y3;
        #pragma unroll
        for (int o = 16; o; o >>= 1) {
            sum += __shfl_xor_sync(0xffffffffu, sum, o);
            sq  += __shfl_xor_sync(0xffffffffu, sq, o);
        }
        const int wdx = t >> 5;
        if ((t & 31) == 0) { rs[wdx] = sum; rq[wdx] = sq; }
        __syncthreads();
        float ts = 0.f, tq = 0.f;
        #pragma unroll
        for (int i = 0; i < 8; i++) { ts += rs[i]; tq += rq[i]; }
        const float m = ts * (1.f/1024.f);
        const float inv = rsqrtf(tq * (1.f/1024.f) - m*m + 1e-5f);
        float4 o;
        o.x = (y0-m)*inv*lg.x + lb.x;
        o.y = (y1-m)*inv*lg.y + lb.y;
        o.z = (y2-m)*inv*lg.z + lb.z;
        o.w = (y3-m)*inv*lg.w + lb.w;
        ((float4*)(out + (size_t)token * 1024))[t] = o;
    }
}

// ---------------- launch --------------------------------------------------
extern "C" void kernel_launch(void* const* d_in, const int* in_sizes, int n_in,
                              void* d_out, int out_size)
{
    const float* x     = (const float*)d_in[0];
    const float* W_ez  = (const float*)d_in[1];
    const float* b_ez  = (const float*)d_in[2];
    const float* U_h   = (const float*)d_in[3];
    const float* U_z   = (const float*)d_in[4];
    const float* b_u   = (const float*)d_in[5];
    const float* osh   = (const float*)d_in[6];
    const float* lns_g = (const float*)d_in[7];
    const float* lns_b = (const float*)d_in[8];
    const float* ffg   = (const float*)d_in[9];
    const float* ffb   = (const float*)d_in[10];
    const float* W1    = (const float*)d_in[11];
    const float* b1    = (const float*)d_in[12];
    const float* W2    = (const float*)d_in[13];
    const float* b2    = (const float*)d_in[14];
    const float* watt  = (const float*)d_in[15];
    const float* batt  = (const float*)d_in[16];
    const float* lno_g = (const float*)d_in[17];
    const float* lno_b = (const float*)d_in[18];
    float* out = (float*)d_out;

    float *gz, *gh1, *gwpre, *gwezr, *gw2r, *gw1r;
    cudaGetSymbolAddress((void**)&gz,    g_z);
    cudaGetSymbolAddress((void**)&gh1,   g_h1);
    cudaGetSymbolAddress((void**)&gwpre, g_wpre);
    cudaGetSymbolAddress((void**)&gwezr, g_wezr);
    cudaGetSymbolAddress((void**)&gw2r,  g_w2r);
    cudaGetSymbolAddress((void**)&gw1r,  g_w1r);

    cudaFuncSetAttribute((const void*)gemm_tf32<1,1>, cudaFuncAttributeMaxDynamicSharedMemorySize, GEMM_SMEM_BYTES);
    cudaFuncSetAttribute((const void*)gemm_tf32<0,0>, cudaFuncAttributeMaxDynamicSharedMemorySize, GEMM_SMEM_BYTES);
    cudaFuncSetAttribute(ffn1_kernel,  cudaFuncAttributeMaxDynamicSharedMemorySize, FFN_SMEM_BYTES);

    // pre-round weights to tf32 (unbiased RNA); x is rounded inside GEMM1
    round_tf32_kernel<<<1024, 256>>>((const float4*)W_ez, (float4*)gwezr, EMB*HD/4);
    round_tf32_kernel<<<1024, 256>>>((const float4*)W2,   (float4*)gw2r,  HD*EMB/4);
    round_tf32_kernel<<<128,  256>>>((const float4*)W1,   (float4*)gw1r,  HD*DIM/4);

    prep_kernel<<<130, 256>>>(W2, b2, watt, osh);

    dim3 gg(8, 64);  // (N/128, M/128)
    gemm_tf32<1,1><<<gg, 256, GEMM_SMEM_BYTES>>>(x, gwezr, b_ez, gz);

    scan_kernel<<<32, 32>>>(U_h, U_z, b_u, lns_g, lns_b, ffg, ffb);

    dim3 gf(64, 8);  // (M/128, heads)
    ffn1_kernel<<<gf, 256, FFN_SMEM_BYTES>>>(gw1r, b1, batt);

    softscale_kernel<<<8192, 128>>>();

    gemm_tf32<0,0><<<gg, 256, GEMM_SMEM_BYTES>>>(gh1, gw2r, nullptr, gwpre);

    final_kernel<<<512, 256>>>(b2, lno_g, lno_b, out);
}